// round 7
// baseline (speedup 1.0000x reference)
#include <cuda_runtime.h>
#include <cstdint>

// ---------------------------------------------------------------------------
// RSSMCore: T=64 sequential steps, B=256.  PASSING MODEL (round 6, locked):
//  * RNG: jax_threefry_partitionable: bits(i) = o0^o1 of threefry(key,(0,i)).
//  * GEMM: exact f32, per-output ascending-k single-accumulator FMA chain.
//  * z weights w = fl(1+p)-p carried into the W_in gather.
//  * XLA rational tanh / logistic / cephes exp/log, FMA-form.
// Round 7: performance only — bit-identical arithmetic, faster GEMM:
//  * 64x128 tile, 4x8/thread (FMA:LDS 32:3 per kk -> FMA-bound, was LDS-bound)
//  * As padded [16][68] -> kills 16-way bank conflict on transposed store
//  * grid.z-merged GEMM pairs (gi|gh, p1|q1, prior|post); concat fused into
//    q1's A-tile load (g_cat eliminated).
// ---------------------------------------------------------------------------

#define T_STEPS 64
#define B 256
#define GRU_H 2048
#define MLP 1000
#define ZF 1024
#define FDIM 1024
#define G3 (3 * GRU_H)   // 6144

// ---------------- scratch (device globals; no allocation allowed) ----------
__device__ float g_x[B * MLP];
__device__ float g_gi[B * G3];
__device__ float g_gh[B * G3];
__device__ float g_h[B * GRU_H];
__device__ float g_p1[B * MLP];
__device__ float g_q1[B * MLP];
__device__ int   g_zidx[B * 32];
__device__ float g_zw[B * 32];

// =================== XLA-matched elementwise math (FMA form) ================

__device__ __forceinline__ float xla_tanh(float x) {
    if (fabsf(x) < 0.0004f) return x;
    float xc = fminf(fmaxf(x, -7.90531110763549805f), 7.90531110763549805f);
    float x2 = __fmul_rn(xc, xc);
    float p = -2.76076847742355e-16f;
    p = __fmaf_rn(p, x2, 2.00018790482477e-13f);
    p = __fmaf_rn(p, x2, -8.60467152213735e-11f);
    p = __fmaf_rn(p, x2, 5.12229709037114e-08f);
    p = __fmaf_rn(p, x2, 1.48572235717979e-05f);
    p = __fmaf_rn(p, x2, 6.37261928875436e-04f);
    p = __fmaf_rn(p, x2, 4.89352455891786e-03f);
    p = __fmul_rn(p, xc);
    float q = 1.19825839466702e-06f;
    q = __fmaf_rn(q, x2, 1.18534705686654e-04f);
    q = __fmaf_rn(q, x2, 2.26843463243900e-03f);
    q = __fmaf_rn(q, x2, 4.89352518554385e-03f);
    return __fdiv_rn(p, q);
}

__device__ __forceinline__ float xla_sigmoid(float x) {
    return __fmaf_rn(0.5f, xla_tanh(__fmul_rn(0.5f, x)), 0.5f);
}

__device__ __forceinline__ float xla_log(float a) {
    int ix = __float_as_int(a);
    float e = (float)((ix >> 23) - 126);
    float m = __int_as_float((ix & 0x007fffff) | 0x3f000000);
    if (m < 0.707106781186547524f) { e = __fadd_rn(e, -1.0f); m = __fadd_rn(m, m); }
    m = __fadd_rn(m, -1.0f);
    float z = __fmul_rn(m, m);
    float y = 7.0376836292e-2f;
    y = __fmaf_rn(y, m, -1.1514610310e-1f);
    y = __fmaf_rn(y, m, 1.1676998740e-1f);
    y = __fmaf_rn(y, m, -1.2420140846e-1f);
    y = __fmaf_rn(y, m, 1.4249322787e-1f);
    y = __fmaf_rn(y, m, -1.6668057665e-1f);
    y = __fmaf_rn(y, m, 2.0000714765e-1f);
    y = __fmaf_rn(y, m, -2.4999993993e-1f);
    y = __fmaf_rn(y, m, 3.3333331174e-1f);
    y = __fmul_rn(__fmul_rn(y, m), z);
    y = __fmaf_rn(e, -2.12194440e-4f, y);
    y = __fmaf_rn(z, -0.5f, y);
    float r = __fadd_rn(m, y);
    r = __fmaf_rn(e, 0.693359375f, r);
    return r;
}

__device__ __forceinline__ float xla_exp(float x) {
    float xc = fminf(fmaxf(x, -87.33654f), 88.72283f);
    float m = floorf(__fmaf_rn(xc, 1.44269504088896341f, 0.5f));
    float r = __fmaf_rn(m, -0.693359375f, xc);
    r = __fmaf_rn(m, 2.12194440e-4f, r);
    float r2 = __fmul_rn(r, r);
    float p = 1.9875691500e-4f;
    p = __fmaf_rn(p, r, 1.3981999507e-3f);
    p = __fmaf_rn(p, r, 8.3334519073e-3f);
    p = __fmaf_rn(p, r, 4.1665795894e-2f);
    p = __fmaf_rn(p, r, 1.6666665459e-1f);
    p = __fmaf_rn(p, r, 5.0000001201e-1f);
    float y = __fadd_rn(__fmaf_rn(p, r2, r), 1.0f);
    return __fmul_rn(y, __int_as_float(((int)m + 127) << 23));
}

__device__ __forceinline__ float xla_expm1(float x) {
    if (fabsf(x) < 1e-5f) return __fmaf_rn(__fmul_rn(0.5f, x), x, x);
    return __fadd_rn(xla_exp(x), -1.0f);
}

__device__ __forceinline__ float xla_elu(float x) {
    return (x > 0.0f) ? x : xla_expm1(x);
}

// ---------------- threefry2x32 (JAX bit-exact) ------------------------------
__device__ __forceinline__ uint32_t rotl32(uint32_t v, int r) {
    return (v << r) | (v >> (32 - r));
}

__device__ __forceinline__ void threefry2x32(uint32_t k0, uint32_t k1,
                                             uint32_t x0, uint32_t x1,
                                             uint32_t& o0, uint32_t& o1) {
    uint32_t ks2 = k0 ^ k1 ^ 0x1BD11BDAu;
    x0 += k0; x1 += k1;
    x0 += x1; x1 = rotl32(x1, 13); x1 ^= x0;
    x0 += x1; x1 = rotl32(x1, 15); x1 ^= x0;
    x0 += x1; x1 = rotl32(x1, 26); x1 ^= x0;
    x0 += x1; x1 = rotl32(x1,  6); x1 ^= x0;
    x0 += k1; x1 += ks2 + 1u;
    x0 += x1; x1 = rotl32(x1, 17); x1 ^= x0;
    x0 += x1; x1 = rotl32(x1, 29); x1 ^= x0;
    x0 += x1; x1 = rotl32(x1, 16); x1 ^= x0;
    x0 += x1; x1 = rotl32(x1, 24); x1 ^= x0;
    x0 += ks2; x1 += k0 + 2u;
    x0 += x1; x1 = rotl32(x1, 13); x1 ^= x0;
    x0 += x1; x1 = rotl32(x1, 15); x1 ^= x0;
    x0 += x1; x1 = rotl32(x1, 26); x1 ^= x0;
    x0 += x1; x1 = rotl32(x1,  6); x1 ^= x0;
    x0 += k0; x1 += k1 + 3u;
    x0 += x1; x1 = rotl32(x1, 17); x1 ^= x0;
    x0 += x1; x1 = rotl32(x1, 29); x1 ^= x0;
    x0 += x1; x1 = rotl32(x1, 16); x1 ^= x0;
    x0 += x1; x1 = rotl32(x1, 24); x1 ^= x0;
    x0 += k1; x1 += ks2 + 4u;
    x0 += x1; x1 = rotl32(x1, 13); x1 ^= x0;
    x0 += x1; x1 = rotl32(x1, 15); x1 ^= x0;
    x0 += x1; x1 = rotl32(x1, 26); x1 ^= x0;
    x0 += x1; x1 = rotl32(x1,  6); x1 ^= x0;
    x0 += ks2; x1 += k0 + 5u;
    o0 = x0; o1 = x1;
}

__device__ __forceinline__ uint32_t jax_bits32(uint32_t k0, uint32_t k1, uint32_t i) {
    uint32_t o0, o1;
    threefry2x32(k0, k1, 0u, i, o0, o1);
    return o0 ^ o1;
}

// ---------------- merged dual SGEMM: 64x128 tile, 4x8/thread ----------------
// blockIdx.z selects GEMM {0,1}. Per output: ascending-k single-accumulator
// FMA chain (bit-identical to the round-6 kernel: same BK=16, same order).
// z==1 with concatK>0: A columns >= concatK come from feat (fused concat).
__global__ __launch_bounds__(256) void gemm2_kernel(
    const float* __restrict__ A0, const float* __restrict__ A1,
    const float* __restrict__ W0, const float* __restrict__ W1,
    const float* __restrict__ b0, const float* __restrict__ b1,
    float* __restrict__ C0, float* __restrict__ C1,
    int K0, int K1, int N, int act,
    const float* __restrict__ feat, int concatK)
{
    __shared__ float As[16][68];    // padded: kills bank conflicts on store
    __shared__ float Ws[16][128];

    const int z  = blockIdx.z;
    const float* A = z ? A1 : A0;
    const float* W = z ? W1 : W0;
    const float* bias = z ? b1 : b0;
    float* C = z ? C1 : C0;
    const int K = z ? K1 : K0;
    const int lda = (z && concatK > 0) ? concatK : K;   // A row stride (h part)

    const int bm = blockIdx.x * 64;
    const int bn = blockIdx.y * 128;
    const int tid = threadIdx.x;
    const int tx = tid & 15;    // 16 col-groups of 8
    const int ty = tid >> 4;    // 16 row-groups of 4

    float acc[4][8];
#pragma unroll
    for (int i = 0; i < 4; i++)
#pragma unroll
        for (int j = 0; j < 8; j++) acc[i][j] = 0.f;

    const bool fullN = (bn + 128 <= N);

    for (int k0 = 0; k0 < K; k0 += 16) {
        // A tile: 64 rows x 16 k, transposed store As[c][r]
#pragma unroll
        for (int l = 0; l < 4; l++) {
            int e = tid + l * 256;
            int r = e >> 4, c = e & 15;
            int k = k0 + c;
            float v = 0.f;
            if (k < K) {
                if (z && concatK > 0 && k >= concatK)
                    v = feat[(size_t)(bm + r) * FDIM + (k - concatK)];
                else
                    v = A[(size_t)(bm + r) * lda + k];
            }
            As[c][r] = v;
        }
        // W tile: 16 k x 128 cols
#pragma unroll
        for (int l = 0; l < 8; l++) {
            int e = tid + l * 256;
            int r = e >> 7, c = e & 127;
            int k = k0 + r, col = bn + c;
            float v = 0.f;
            if (k < K && col < N) v = W[(size_t)k * N + col];
            Ws[r][c] = v;
        }
        __syncthreads();
#pragma unroll
        for (int kk = 0; kk < 16; kk++) {
            float4 av  = *reinterpret_cast<const float4*>(&As[kk][ty * 4]);
            float4 wv0 = *reinterpret_cast<const float4*>(&Ws[kk][tx * 8]);
            float4 wv1 = *reinterpret_cast<const float4*>(&Ws[kk][tx * 8 + 4]);
            float a_[4] = {av.x, av.y, av.z, av.w};
            float w_[8] = {wv0.x, wv0.y, wv0.z, wv0.w, wv1.x, wv1.y, wv1.z, wv1.w};
#pragma unroll
            for (int i = 0; i < 4; i++)
#pragma unroll
                for (int j = 0; j < 8; j++)
                    acc[i][j] = __fmaf_rn(a_[i], w_[j], acc[i][j]);
        }
        __syncthreads();
    }

#pragma unroll
    for (int i = 0; i < 4; i++) {
        int row = bm + ty * 4 + i;
        int colb = bn + tx * 8;
        float v[8];
#pragma unroll
        for (int j = 0; j < 8; j++) {
            float x = acc[i][j];
            int col = colb + j;
            if (col < N) {
                if (bias) x = __fadd_rn(x, bias[col]);
                if (act) x = xla_elu(x);
            }
            v[j] = x;
        }
        if (fullN) {
            float4* dst = reinterpret_cast<float4*>(&C[(size_t)row * N + colb]);
            dst[0] = make_float4(v[0], v[1], v[2], v[3]);
            dst[1] = make_float4(v[4], v[5], v[6], v[7]);
        } else {
#pragma unroll
            for (int j = 0; j < 8; j++)
                if (colb + j < N) C[(size_t)row * N + colb + j] = v[j];
        }
    }
}

// ---------------- x = elu(weighted gather of W_in rows + b_in) -------------
__global__ __launch_bounds__(256) void compute_x_kernel(
    const float* __restrict__ W_in, const float* __restrict__ b_in,
    const int* __restrict__ actions, int t)
{
    int b = blockIdx.x;
    int a = (t == 0) ? 0 : actions[(t - 1) * B + b];
    __shared__ int idx[32];
    __shared__ float wgt[32];
    if (threadIdx.x < 32) {
        idx[threadIdx.x] = (t == 0) ? 0 : g_zidx[b * 32 + threadIdx.x];
        wgt[threadIdx.x] = (t == 0) ? 0.f : g_zw[b * 32 + threadIdx.x];
    }
    __syncthreads();
    for (int j = threadIdx.x; j < MLP; j += blockDim.x) {
        float s = 0.f;
        if (t > 0) {
#pragma unroll
            for (int c = 0; c < 32; c++)
                s = __fmaf_rn(wgt[c], W_in[(size_t)(c * 32 + idx[c]) * MLP + j], s);
        }
        s = __fmaf_rn(1.0f, W_in[(size_t)(ZF + a) * MLP + j], s);
        s = __fadd_rn(s, b_in[j]);
        g_x[b * MLP + j] = xla_elu(s);
    }
}

// ---------------- GRU gate pointwise ----------------------------------------
__global__ __launch_bounds__(256) void gru_kernel()
{
    int i = blockIdx.x * blockDim.x + threadIdx.x;  // [0, B*GRU_H)
    int b = i >> 11, j = i & (GRU_H - 1);
    const float* gib = g_gi + (size_t)b * G3;
    const float* ghb = g_gh + (size_t)b * G3;
    float ir = gib[j],              hr = ghb[j];
    float iz = gib[GRU_H + j],      hz = ghb[GRU_H + j];
    float in_ = gib[2 * GRU_H + j], hn = ghb[2 * GRU_H + j];
    float r  = xla_sigmoid(__fadd_rn(ir, hr));
    float zg = xla_sigmoid(__fadd_rn(iz, hz));
    float n  = xla_tanh(__fmaf_rn(r, hn, in_));
    float hp = g_h[i];
    g_h[i] = __fmaf_rn(zg, hp, __fmul_rn(__fsub_rn(1.0f, zg), n));
}

__global__ __launch_bounds__(256) void zero_h_kernel()
{
    int i = blockIdx.x * blockDim.x + threadIdx.x;
    if (i < B * GRU_H) g_h[i] = 0.f;
}

// ---------------- categorical sample + straight-through weight --------------
__global__ __launch_bounds__(256) void sample_kernel(
    const float* __restrict__ post, int t)
{
    int b = blockIdx.x;
    int warp = threadIdx.x >> 5;
    int lane = threadIdx.x & 31;
    uint32_t k0, k1;
    threefry2x32(0u, 42u, 0u, (uint32_t)t, k0, k1);   // fold_in(key(42), t)

    const float TINY = 1.1754943508222875e-38f;

    for (int c = warp; c < 32; c += 8) {
        float l = post[(size_t)b * ZF + c * 32 + lane];

        uint32_t i = (uint32_t)((b * 32 + c) * 32 + lane);
        uint32_t bits = jax_bits32(k0, k1, i);
        float f = __fadd_rn(__uint_as_float((bits >> 9) | 0x3f800000u), -1.0f);
        float u = fmaxf(TINY, __fadd_rn(f, TINY));
        float g = -xla_log(-xla_log(u));
        float v = __fadd_rn(l, g);

        float bv = v; int bi = lane;
#pragma unroll
        for (int off = 16; off > 0; off >>= 1) {
            float ov = __shfl_down_sync(0xffffffffu, bv, off);
            int   oi = __shfl_down_sync(0xffffffffu, bi, off);
            if (ov > bv || (ov == bv && oi < bi)) { bv = ov; bi = oi; }
        }
        bi = __shfl_sync(0xffffffffu, bi, 0);

        float m = l;
#pragma unroll
        for (int off = 16; off > 0; off >>= 1)
            m = fmaxf(m, __shfl_xor_sync(0xffffffffu, m, off));
        float e = xla_exp(__fadd_rn(l, -m));
        float s = 0.f;
#pragma unroll
        for (int ll = 0; ll < 32; ll++)
            s = __fadd_rn(s, __shfl_sync(0xffffffffu, e, ll));
        float p = __fdiv_rn(e, s);
        float psel = __shfl_sync(0xffffffffu, p, bi);
        if (lane == 0) {
            float w = __fadd_rn(__fadd_rn(1.0f, psel), -psel);  // fl(1+p)-p
            g_zidx[b * 32 + c] = bi;
            g_zw[b * 32 + c] = w;
        }
    }
}

// ---------------------------------------------------------------------------
extern "C" void kernel_launch(void* const* d_in, const int* in_sizes, int n_in,
                              void* d_out, int out_size)
{
    const float* features = (const float*)d_in[0];   // [64,256,1024]
    const int*   actions  = (const int*)  d_in[1];   // [64,256]
    const float* W_in = (const float*)d_in[2];       // [1030,1000]
    const float* b_in = (const float*)d_in[3];
    const float* W_ih = (const float*)d_in[4];       // [1000,6144]
    const float* W_hh = (const float*)d_in[5];       // [2048,6144]
    const float* b_ih = (const float*)d_in[6];
    const float* b_hh = (const float*)d_in[7];
    const float* Wp1  = (const float*)d_in[8];       // [2048,1000]
    const float* bp1  = (const float*)d_in[9];
    const float* Wp2  = (const float*)d_in[10];      // [1000,1024]
    const float* bp2  = (const float*)d_in[11];
    const float* Wq1  = (const float*)d_in[12];      // [3072,1000]
    const float* bq1  = (const float*)d_in[13];
    const float* Wq2  = (const float*)d_in[14];      // [1000,1024]
    const float* bq2  = (const float*)d_in[15];
    float* out = (float*)d_out;                      // [2,64,256,32,32]

    float *px, *pgi, *pgh, *ph, *pp1, *pq1;
    cudaGetSymbolAddress((void**)&px,  g_x);
    cudaGetSymbolAddress((void**)&pgi, g_gi);
    cudaGetSymbolAddress((void**)&pgh, g_gh);
    cudaGetSymbolAddress((void**)&ph,  g_h);
    cudaGetSymbolAddress((void**)&pp1, g_p1);
    cudaGetSymbolAddress((void**)&pq1, g_q1);

    zero_h_kernel<<<(B * GRU_H + 255) / 256, 256>>>();

    for (int t = 0; t < T_STEPS; t++) {
        const float* feat_t = features + (size_t)t * B * FDIM;
        float* out_prior = out + (size_t)t * B * ZF;
        float* out_post  = out + ((size_t)(T_STEPS + t)) * B * ZF;

        compute_x_kernel<<<B, 256>>>(W_in, b_in, actions, t);

        // gi = x @ W_ih + b_ih  |  gh = h @ W_hh + b_hh   (N=6144)
        gemm2_kernel<<<dim3(B / 64, G3 / 128, 2), 256>>>(
            px, ph, W_ih, W_hh, b_ih, b_hh, pgi, pgh,
            MLP, GRU_H, G3, 0, nullptr, 0);

        gru_kernel<<<(B * GRU_H) / 256, 256>>>();

        // p1 = elu(h @ Wp1 + bp1)  |  q1 = elu([h|feat] @ Wq1 + bq1)  (N=1000)
        gemm2_kernel<<<dim3(B / 64, (MLP + 127) / 128, 2), 256>>>(
            ph, ph, Wp1, Wq1, bp1, bq1, pp1, pq1,
            GRU_H, GRU_H + FDIM, MLP, 1, feat_t, GRU_H);

        // prior = p1 @ Wp2 + bp2  |  post = q1 @ Wq2 + bq2   (N=1024)
        gemm2_kernel<<<dim3(B / 64, ZF / 128, 2), 256>>>(
            pp1, pq1, Wp2, Wq2, bp2, bq2, out_prior, out_post,
            MLP, MLP, ZF, 0, nullptr, 0);

        sample_kernel<<<B, 256>>>(out_post, t);
    }
}

// round 8
// speedup vs baseline: 1.3701x; 1.3701x over previous
#include <cuda_runtime.h>
#include <cstdint>

// ---------------------------------------------------------------------------
// RSSMCore: T=64 sequential steps, B=256.  PASSING MODEL (round 6, locked):
//  * RNG: jax_threefry_partitionable: bits(i) = o0^o1 of threefry(key,(0,i)).
//  * GEMM: exact f32, per-output ascending-k single-accumulator FMA chain
//    (BK=16 tiles ascending) — proven flip-free at rel_err 9.05e-07. DO NOT
//    change per-output arithmetic.
//  * z weights w = fl(1+p)-p carried into the W_in gather.
//  * XLA rational tanh / logistic / cephes exp/log, FMA-form.
// Round 8 (perf only, register-neutral):
//  * round-6 64x64/4x4 tile GEMM (64 regs, 4 blocks/SM) kept;
//  * As padded [16][68]: kills the 16-way STS bank conflict (L1 was 74.6%);
//  * grid.z merges GEMM pairs (gi|gh, p1|q1, prior|post) at 64-wide tiles ->
//    small GEMMs go 64 -> 128 blocks;
//  * concat fused into q1 A-load; float4 epilogue on full tiles.
// ---------------------------------------------------------------------------

#define T_STEPS 64
#define B 256
#define GRU_H 2048
#define MLP 1000
#define ZF 1024
#define FDIM 1024
#define G3 (3 * GRU_H)   // 6144

// ---------------- scratch (device globals; no allocation allowed) ----------
__device__ float g_x[B * MLP];
__device__ float g_gi[B * G3];
__device__ float g_gh[B * G3];
__device__ float g_h[B * GRU_H];
__device__ float g_p1[B * MLP];
__device__ float g_q1[B * MLP];
__device__ int   g_zidx[B * 32];
__device__ float g_zw[B * 32];

// =================== XLA-matched elementwise math (FMA form) ================

__device__ __forceinline__ float xla_tanh(float x) {
    if (fabsf(x) < 0.0004f) return x;
    float xc = fminf(fmaxf(x, -7.90531110763549805f), 7.90531110763549805f);
    float x2 = __fmul_rn(xc, xc);
    float p = -2.76076847742355e-16f;
    p = __fmaf_rn(p, x2, 2.00018790482477e-13f);
    p = __fmaf_rn(p, x2, -8.60467152213735e-11f);
    p = __fmaf_rn(p, x2, 5.12229709037114e-08f);
    p = __fmaf_rn(p, x2, 1.48572235717979e-05f);
    p = __fmaf_rn(p, x2, 6.37261928875436e-04f);
    p = __fmaf_rn(p, x2, 4.89352455891786e-03f);
    p = __fmul_rn(p, xc);
    float q = 1.19825839466702e-06f;
    q = __fmaf_rn(q, x2, 1.18534705686654e-04f);
    q = __fmaf_rn(q, x2, 2.26843463243900e-03f);
    q = __fmaf_rn(q, x2, 4.89352518554385e-03f);
    return __fdiv_rn(p, q);
}

__device__ __forceinline__ float xla_sigmoid(float x) {
    return __fmaf_rn(0.5f, xla_tanh(__fmul_rn(0.5f, x)), 0.5f);
}

__device__ __forceinline__ float xla_log(float a) {
    int ix = __float_as_int(a);
    float e = (float)((ix >> 23) - 126);
    float m = __int_as_float((ix & 0x007fffff) | 0x3f000000);
    if (m < 0.707106781186547524f) { e = __fadd_rn(e, -1.0f); m = __fadd_rn(m, m); }
    m = __fadd_rn(m, -1.0f);
    float z = __fmul_rn(m, m);
    float y = 7.0376836292e-2f;
    y = __fmaf_rn(y, m, -1.1514610310e-1f);
    y = __fmaf_rn(y, m, 1.1676998740e-1f);
    y = __fmaf_rn(y, m, -1.2420140846e-1f);
    y = __fmaf_rn(y, m, 1.4249322787e-1f);
    y = __fmaf_rn(y, m, -1.6668057665e-1f);
    y = __fmaf_rn(y, m, 2.0000714765e-1f);
    y = __fmaf_rn(y, m, -2.4999993993e-1f);
    y = __fmaf_rn(y, m, 3.3333331174e-1f);
    y = __fmul_rn(__fmul_rn(y, m), z);
    y = __fmaf_rn(e, -2.12194440e-4f, y);
    y = __fmaf_rn(z, -0.5f, y);
    float r = __fadd_rn(m, y);
    r = __fmaf_rn(e, 0.693359375f, r);
    return r;
}

__device__ __forceinline__ float xla_exp(float x) {
    float xc = fminf(fmaxf(x, -87.33654f), 88.72283f);
    float m = floorf(__fmaf_rn(xc, 1.44269504088896341f, 0.5f));
    float r = __fmaf_rn(m, -0.693359375f, xc);
    r = __fmaf_rn(m, 2.12194440e-4f, r);
    float r2 = __fmul_rn(r, r);
    float p = 1.9875691500e-4f;
    p = __fmaf_rn(p, r, 1.3981999507e-3f);
    p = __fmaf_rn(p, r, 8.3334519073e-3f);
    p = __fmaf_rn(p, r, 4.1665795894e-2f);
    p = __fmaf_rn(p, r, 1.6666665459e-1f);
    p = __fmaf_rn(p, r, 5.0000001201e-1f);
    float y = __fadd_rn(__fmaf_rn(p, r2, r), 1.0f);
    return __fmul_rn(y, __int_as_float(((int)m + 127) << 23));
}

__device__ __forceinline__ float xla_expm1(float x) {
    if (fabsf(x) < 1e-5f) return __fmaf_rn(__fmul_rn(0.5f, x), x, x);
    return __fadd_rn(xla_exp(x), -1.0f);
}

__device__ __forceinline__ float xla_elu(float x) {
    return (x > 0.0f) ? x : xla_expm1(x);
}

// ---------------- threefry2x32 (JAX bit-exact) ------------------------------
__device__ __forceinline__ uint32_t rotl32(uint32_t v, int r) {
    return (v << r) | (v >> (32 - r));
}

__device__ __forceinline__ void threefry2x32(uint32_t k0, uint32_t k1,
                                             uint32_t x0, uint32_t x1,
                                             uint32_t& o0, uint32_t& o1) {
    uint32_t ks2 = k0 ^ k1 ^ 0x1BD11BDAu;
    x0 += k0; x1 += k1;
    x0 += x1; x1 = rotl32(x1, 13); x1 ^= x0;
    x0 += x1; x1 = rotl32(x1, 15); x1 ^= x0;
    x0 += x1; x1 = rotl32(x1, 26); x1 ^= x0;
    x0 += x1; x1 = rotl32(x1,  6); x1 ^= x0;
    x0 += k1; x1 += ks2 + 1u;
    x0 += x1; x1 = rotl32(x1, 17); x1 ^= x0;
    x0 += x1; x1 = rotl32(x1, 29); x1 ^= x0;
    x0 += x1; x1 = rotl32(x1, 16); x1 ^= x0;
    x0 += x1; x1 = rotl32(x1, 24); x1 ^= x0;
    x0 += ks2; x1 += k0 + 2u;
    x0 += x1; x1 = rotl32(x1, 13); x1 ^= x0;
    x0 += x1; x1 = rotl32(x1, 15); x1 ^= x0;
    x0 += x1; x1 = rotl32(x1, 26); x1 ^= x0;
    x0 += x1; x1 = rotl32(x1,  6); x1 ^= x0;
    x0 += k0; x1 += k1 + 3u;
    x0 += x1; x1 = rotl32(x1, 17); x1 ^= x0;
    x0 += x1; x1 = rotl32(x1, 29); x1 ^= x0;
    x0 += x1; x1 = rotl32(x1, 16); x1 ^= x0;
    x0 += x1; x1 = rotl32(x1, 24); x1 ^= x0;
    x0 += k1; x1 += ks2 + 4u;
    x0 += x1; x1 = rotl32(x1, 13); x1 ^= x0;
    x0 += x1; x1 = rotl32(x1, 15); x1 ^= x0;
    x0 += x1; x1 = rotl32(x1, 26); x1 ^= x0;
    x0 += x1; x1 = rotl32(x1,  6); x1 ^= x0;
    x0 += ks2; x1 += k0 + 5u;
    o0 = x0; o1 = x1;
}

__device__ __forceinline__ uint32_t jax_bits32(uint32_t k0, uint32_t k1, uint32_t i) {
    uint32_t o0, o1;
    threefry2x32(k0, k1, 0u, i, o0, o1);
    return o0 ^ o1;
}

// ---------------- merged dual SGEMM: 64x64 tile, 4x4/thread -----------------
// blockIdx.z selects GEMM {0,1}. Per-output arithmetic IDENTICAL to round 6:
// ascending-k single-accumulator FMA chain over BK=16 tiles.
// z==1 with concatK>0: A columns >= concatK come from feat (fused concat).
__global__ __launch_bounds__(256) void gemm2_kernel(
    const float* __restrict__ A0, const float* __restrict__ A1,
    const float* __restrict__ W0, const float* __restrict__ W1,
    const float* __restrict__ b0, const float* __restrict__ b1,
    float* __restrict__ C0, float* __restrict__ C1,
    int K0, int K1, int N, int act,
    const float* __restrict__ feat, int concatK)
{
    __shared__ float As[16][68];    // pad 68: 16-way -> 2-way store conflict
    __shared__ float Ws[16][64];

    const int z  = blockIdx.z;
    const float* A = z ? A1 : A0;
    const float* W = z ? W1 : W0;
    const float* bias = z ? b1 : b0;
    float* C = z ? C1 : C0;
    const int K = z ? K1 : K0;
    const int lda = (z && concatK > 0) ? concatK : K;   // A row stride (h part)
    const bool fuse = (z && concatK > 0);

    const int bm = blockIdx.x * 64;
    const int bn = blockIdx.y * 64;
    const int tid = threadIdx.x;
    const int tx = tid & 15;
    const int ty = tid >> 4;

    float acc[4][4];
#pragma unroll
    for (int i = 0; i < 4; i++)
#pragma unroll
        for (int j = 0; j < 4; j++) acc[i][j] = 0.f;

    const bool fullN = (bn + 64 <= N);

    for (int k0 = 0; k0 < K; k0 += 16) {
        // A tile: 64 rows x 16 k, transposed store As[c][r] (padded row)
#pragma unroll
        for (int l = 0; l < 4; l++) {
            int e = tid + l * 256;
            int r = e >> 4, c = e & 15;
            int k = k0 + c;
            float v = 0.f;
            if (k < K) {
                if (fuse && k >= concatK)
                    v = feat[(size_t)(bm + r) * FDIM + (k - concatK)];
                else
                    v = A[(size_t)(bm + r) * lda + k];
            }
            As[c][r] = v;
        }
        // W tile: 16 k x 64 cols
#pragma unroll
        for (int l = 0; l < 4; l++) {
            int e = tid + l * 256;
            int r = e >> 6, c = e & 63;
            int k = k0 + r, col = bn + c;
            float v = 0.f;
            if (k < K && col < N) v = W[(size_t)k * N + col];
            Ws[r][c] = v;
        }
        __syncthreads();
#pragma unroll
        for (int kk = 0; kk < 16; kk++) {
            float4 av = *reinterpret_cast<const float4*>(&As[kk][ty * 4]);
            float4 wv = *reinterpret_cast<const float4*>(&Ws[kk][tx * 4]);
            float a_[4] = {av.x, av.y, av.z, av.w};
            float w_[4] = {wv.x, wv.y, wv.z, wv.w};
#pragma unroll
            for (int i = 0; i < 4; i++)
#pragma unroll
                for (int j = 0; j < 4; j++)
                    acc[i][j] = __fmaf_rn(a_[i], w_[j], acc[i][j]);
        }
        __syncthreads();
    }

#pragma unroll
    for (int i = 0; i < 4; i++) {
        int row = bm + ty * 4 + i;
        int colb = bn + tx * 4;
        float v[4];
#pragma unroll
        for (int j = 0; j < 4; j++) {
            float x = acc[i][j];
            int col = colb + j;
            if (col < N) {
                if (bias) x = __fadd_rn(x, bias[col]);
                if (act) x = xla_elu(x);
            }
            v[j] = x;
        }
        if (fullN) {
            *reinterpret_cast<float4*>(&C[(size_t)row * N + colb]) =
                make_float4(v[0], v[1], v[2], v[3]);
        } else {
#pragma unroll
            for (int j = 0; j < 4; j++)
                if (colb + j < N) C[(size_t)row * N + colb + j] = v[j];
        }
    }
}

// ---------------- x = elu(weighted gather of W_in rows + b_in) -------------
__global__ __launch_bounds__(256) void compute_x_kernel(
    const float* __restrict__ W_in, const float* __restrict__ b_in,
    const int* __restrict__ actions, int t)
{
    int b = blockIdx.x;
    int a = (t == 0) ? 0 : actions[(t - 1) * B + b];
    __shared__ int idx[32];
    __shared__ float wgt[32];
    if (threadIdx.x < 32) {
        idx[threadIdx.x] = (t == 0) ? 0 : g_zidx[b * 32 + threadIdx.x];
        wgt[threadIdx.x] = (t == 0) ? 0.f : g_zw[b * 32 + threadIdx.x];
    }
    __syncthreads();
    for (int j = threadIdx.x; j < MLP; j += blockDim.x) {
        float s = 0.f;
        if (t > 0) {
#pragma unroll
            for (int c = 0; c < 32; c++)
                s = __fmaf_rn(wgt[c], W_in[(size_t)(c * 32 + idx[c]) * MLP + j], s);
        }
        s = __fmaf_rn(1.0f, W_in[(size_t)(ZF + a) * MLP + j], s);
        s = __fadd_rn(s, b_in[j]);
        g_x[b * MLP + j] = xla_elu(s);
    }
}

// ---------------- GRU gate pointwise ----------------------------------------
__global__ __launch_bounds__(256) void gru_kernel()
{
    int i = blockIdx.x * blockDim.x + threadIdx.x;  // [0, B*GRU_H)
    int b = i >> 11, j = i & (GRU_H - 1);
    const float* gib = g_gi + (size_t)b * G3;
    const float* ghb = g_gh + (size_t)b * G3;
    float ir = gib[j],              hr = ghb[j];
    float iz = gib[GRU_H + j],      hz = ghb[GRU_H + j];
    float in_ = gib[2 * GRU_H + j], hn = ghb[2 * GRU_H + j];
    float r  = xla_sigmoid(__fadd_rn(ir, hr));
    float zg = xla_sigmoid(__fadd_rn(iz, hz));
    float n  = xla_tanh(__fmaf_rn(r, hn, in_));
    float hp = g_h[i];
    g_h[i] = __fmaf_rn(zg, hp, __fmul_rn(__fsub_rn(1.0f, zg), n));
}

__global__ __launch_bounds__(256) void zero_h_kernel()
{
    int i = blockIdx.x * blockDim.x + threadIdx.x;
    if (i < B * GRU_H) g_h[i] = 0.f;
}

// ---------------- categorical sample + straight-through weight --------------
__global__ __launch_bounds__(256) void sample_kernel(
    const float* __restrict__ post, int t)
{
    int b = blockIdx.x;
    int warp = threadIdx.x >> 5;
    int lane = threadIdx.x & 31;
    uint32_t k0, k1;
    threefry2x32(0u, 42u, 0u, (uint32_t)t, k0, k1);   // fold_in(key(42), t)

    const float TINY = 1.1754943508222875e-38f;

    for (int c = warp; c < 32; c += 8) {
        float l = post[(size_t)b * ZF + c * 32 + lane];

        uint32_t i = (uint32_t)((b * 32 + c) * 32 + lane);
        uint32_t bits = jax_bits32(k0, k1, i);
        float f = __fadd_rn(__uint_as_float((bits >> 9) | 0x3f800000u), -1.0f);
        float u = fmaxf(TINY, __fadd_rn(f, TINY));
        float g = -xla_log(-xla_log(u));
        float v = __fadd_rn(l, g);

        float bv = v; int bi = lane;
#pragma unroll
        for (int off = 16; off > 0; off >>= 1) {
            float ov = __shfl_down_sync(0xffffffffu, bv, off);
            int   oi = __shfl_down_sync(0xffffffffu, bi, off);
            if (ov > bv || (ov == bv && oi < bi)) { bv = ov; bi = oi; }
        }
        bi = __shfl_sync(0xffffffffu, bi, 0);

        float m = l;
#pragma unroll
        for (int off = 16; off > 0; off >>= 1)
            m = fmaxf(m, __shfl_xor_sync(0xffffffffu, m, off));
        float e = xla_exp(__fadd_rn(l, -m));
        float s = 0.f;
#pragma unroll
        for (int ll = 0; ll < 32; ll++)
            s = __fadd_rn(s, __shfl_sync(0xffffffffu, e, ll));
        float p = __fdiv_rn(e, s);
        float psel = __shfl_sync(0xffffffffu, p, bi);
        if (lane == 0) {
            float w = __fadd_rn(__fadd_rn(1.0f, psel), -psel);  // fl(1+p)-p
            g_zidx[b * 32 + c] = bi;
            g_zw[b * 32 + c] = w;
        }
    }
}

// ---------------------------------------------------------------------------
extern "C" void kernel_launch(void* const* d_in, const int* in_sizes, int n_in,
                              void* d_out, int out_size)
{
    const float* features = (const float*)d_in[0];   // [64,256,1024]
    const int*   actions  = (const int*)  d_in[1];   // [64,256]
    const float* W_in = (const float*)d_in[2];       // [1030,1000]
    const float* b_in = (const float*)d_in[3];
    const float* W_ih = (const float*)d_in[4];       // [1000,6144]
    const float* W_hh = (const float*)d_in[5];       // [2048,6144]
    const float* b_ih = (const float*)d_in[6];
    const float* b_hh = (const float*)d_in[7];
    const float* Wp1  = (const float*)d_in[8];       // [2048,1000]
    const float* bp1  = (const float*)d_in[9];
    const float* Wp2  = (const float*)d_in[10];      // [1000,1024]
    const float* bp2  = (const float*)d_in[11];
    const float* Wq1  = (const float*)d_in[12];      // [3072,1000]
    const float* bq1  = (const float*)d_in[13];
    const float* Wq2  = (const float*)d_in[14];      // [1000,1024]
    const float* bq2  = (const float*)d_in[15];
    float* out = (float*)d_out;                      // [2,64,256,32,32]

    float *px, *pgi, *pgh, *ph, *pp1, *pq1;
    cudaGetSymbolAddress((void**)&px,  g_x);
    cudaGetSymbolAddress((void**)&pgi, g_gi);
    cudaGetSymbolAddress((void**)&pgh, g_gh);
    cudaGetSymbolAddress((void**)&ph,  g_h);
    cudaGetSymbolAddress((void**)&pp1, g_p1);
    cudaGetSymbolAddress((void**)&pq1, g_q1);

    zero_h_kernel<<<(B * GRU_H + 255) / 256, 256>>>();

    for (int t = 0; t < T_STEPS; t++) {
        const float* feat_t = features + (size_t)t * B * FDIM;
        float* out_prior = out + (size_t)t * B * ZF;
        float* out_post  = out + ((size_t)(T_STEPS + t)) * B * ZF;

        compute_x_kernel<<<B, 256>>>(W_in, b_in, actions, t);

        // gi = x @ W_ih + b_ih  |  gh = h @ W_hh + b_hh   (N=6144)
        gemm2_kernel<<<dim3(B / 64, G3 / 64, 2), 256>>>(
            px, ph, W_ih, W_hh, b_ih, b_hh, pgi, pgh,
            MLP, GRU_H, G3, 0, nullptr, 0);

        gru_kernel<<<(B * GRU_H) / 256, 256>>>();

        // p1 = elu(h @ Wp1 + bp1)  |  q1 = elu([h|feat] @ Wq1 + bq1)  (N=1000)
        gemm2_kernel<<<dim3(B / 64, (MLP + 63) / 64, 2), 256>>>(
            ph, ph, Wp1, Wq1, bp1, bq1, pp1, pq1,
            GRU_H, GRU_H + FDIM, MLP, 1, feat_t, GRU_H);

        // prior = p1 @ Wp2 + bp2  |  post = q1 @ Wq2 + bq2   (N=1024)
        gemm2_kernel<<<dim3(B / 64, ZF / 64, 2), 256>>>(
            pp1, pq1, Wp2, Wq2, bp2, bq2, out_prior, out_post,
            MLP, MLP, ZF, 0, nullptr, 0);

        sample_kernel<<<B, 256>>>(out_post, t);
    }
}

// round 10
// speedup vs baseline: 1.6452x; 1.2008x over previous
#include <cuda_runtime.h>
#include <cstdint>

// ---------------------------------------------------------------------------
// RSSMCore: T=64 sequential steps, B=256.  PASSING MODEL (locked since R6):
//  * RNG: jax_threefry_partitionable: bits(i) = o0^o1 of threefry(key,(0,i)).
//  * GEMM: exact f32, per-output ascending-k single-accumulator FMA chain
//    (BK=16 tiles ascending) — flip-free at rel_err 9.051719e-07.
//    Per-output arithmetic MUST NOT change (thread mapping may).
//  * z weights w = fl(1+p)-p carried into the W_in gather.
//  * XLA rational tanh / logistic / cephes exp/log, FMA-form.
// Round 10 (perf only; R9's streams leaked graph-upload memory -> banned):
//  * GEMM: 64x128 tile, 4x8/thread, N-cols split {tx*4} U {64+tx*4} so BOTH
//    W reads are 16B-lane-stride LDS.128 (conflict-free; R7's 32B stride was
//    2-way conflicted). 1.5 B/FMA -> FMA-bound (4x4 was pinned at the 50%
//    LDS/FMA co-saturation point).
//  * Mega-merge: triple launch [gh_{t+1} | p1 | q1] right after gru (all
//    depend only on h_t) -> heads hide inside the big gh GEMM. Single stream.
// ---------------------------------------------------------------------------

#define T_STEPS 64
#define B 256
#define GRU_H 2048
#define MLP 1000
#define ZF 1024
#define FDIM 1024
#define G3 (3 * GRU_H)   // 6144

// ---------------- scratch (device globals; no allocation allowed) ----------
__device__ float g_x[B * MLP];
__device__ float g_gi[B * G3];
__device__ float g_gh[B * G3];
__device__ float g_h[B * GRU_H];
__device__ float g_p1[B * MLP];
__device__ float g_q1[B * MLP];
__device__ int   g_zidx[B * 32];
__device__ float g_zw[B * 32];

// =================== XLA-matched elementwise math (FMA form) ================

__device__ __forceinline__ float xla_tanh(float x) {
    if (fabsf(x) < 0.0004f) return x;
    float xc = fminf(fmaxf(x, -7.90531110763549805f), 7.90531110763549805f);
    float x2 = __fmul_rn(xc, xc);
    float p = -2.76076847742355e-16f;
    p = __fmaf_rn(p, x2, 2.00018790482477e-13f);
    p = __fmaf_rn(p, x2, -8.60467152213735e-11f);
    p = __fmaf_rn(p, x2, 5.12229709037114e-08f);
    p = __fmaf_rn(p, x2, 1.48572235717979e-05f);
    p = __fmaf_rn(p, x2, 6.37261928875436e-04f);
    p = __fmaf_rn(p, x2, 4.89352455891786e-03f);
    p = __fmul_rn(p, xc);
    float q = 1.19825839466702e-06f;
    q = __fmaf_rn(q, x2, 1.18534705686654e-04f);
    q = __fmaf_rn(q, x2, 2.26843463243900e-03f);
    q = __fmaf_rn(q, x2, 4.89352518554385e-03f);
    return __fdiv_rn(p, q);
}

__device__ __forceinline__ float xla_sigmoid(float x) {
    return __fmaf_rn(0.5f, xla_tanh(__fmul_rn(0.5f, x)), 0.5f);
}

__device__ __forceinline__ float xla_log(float a) {
    int ix = __float_as_int(a);
    float e = (float)((ix >> 23) - 126);
    float m = __int_as_float((ix & 0x007fffff) | 0x3f000000);
    if (m < 0.707106781186547524f) { e = __fadd_rn(e, -1.0f); m = __fadd_rn(m, m); }
    m = __fadd_rn(m, -1.0f);
    float z = __fmul_rn(m, m);
    float y = 7.0376836292e-2f;
    y = __fmaf_rn(y, m, -1.1514610310e-1f);
    y = __fmaf_rn(y, m, 1.1676998740e-1f);
    y = __fmaf_rn(y, m, -1.2420140846e-1f);
    y = __fmaf_rn(y, m, 1.4249322787e-1f);
    y = __fmaf_rn(y, m, -1.6668057665e-1f);
    y = __fmaf_rn(y, m, 2.0000714765e-1f);
    y = __fmaf_rn(y, m, -2.4999993993e-1f);
    y = __fmaf_rn(y, m, 3.3333331174e-1f);
    y = __fmul_rn(__fmul_rn(y, m), z);
    y = __fmaf_rn(e, -2.12194440e-4f, y);
    y = __fmaf_rn(z, -0.5f, y);
    float r = __fadd_rn(m, y);
    r = __fmaf_rn(e, 0.693359375f, r);
    return r;
}

__device__ __forceinline__ float xla_exp(float x) {
    float xc = fminf(fmaxf(x, -87.33654f), 88.72283f);
    float m = floorf(__fmaf_rn(xc, 1.44269504088896341f, 0.5f));
    float r = __fmaf_rn(m, -0.693359375f, xc);
    r = __fmaf_rn(m, 2.12194440e-4f, r);
    float r2 = __fmul_rn(r, r);
    float p = 1.9875691500e-4f;
    p = __fmaf_rn(p, r, 1.3981999507e-3f);
    p = __fmaf_rn(p, r, 8.3334519073e-3f);
    p = __fmaf_rn(p, r, 4.1665795894e-2f);
    p = __fmaf_rn(p, r, 1.6666665459e-1f);
    p = __fmaf_rn(p, r, 5.0000001201e-1f);
    float y = __fadd_rn(__fmaf_rn(p, r2, r), 1.0f);
    return __fmul_rn(y, __int_as_float(((int)m + 127) << 23));
}

__device__ __forceinline__ float xla_expm1(float x) {
    if (fabsf(x) < 1e-5f) return __fmaf_rn(__fmul_rn(0.5f, x), x, x);
    return __fadd_rn(xla_exp(x), -1.0f);
}

__device__ __forceinline__ float xla_elu(float x) {
    return (x > 0.0f) ? x : xla_expm1(x);
}

// ---------------- threefry2x32 (JAX bit-exact) ------------------------------
__device__ __forceinline__ uint32_t rotl32(uint32_t v, int r) {
    return (v << r) | (v >> (32 - r));
}

__device__ __forceinline__ void threefry2x32(uint32_t k0, uint32_t k1,
                                             uint32_t x0, uint32_t x1,
                                             uint32_t& o0, uint32_t& o1) {
    uint32_t ks2 = k0 ^ k1 ^ 0x1BD11BDAu;
    x0 += k0; x1 += k1;
    x0 += x1; x1 = rotl32(x1, 13); x1 ^= x0;
    x0 += x1; x1 = rotl32(x1, 15); x1 ^= x0;
    x0 += x1; x1 = rotl32(x1, 26); x1 ^= x0;
    x0 += x1; x1 = rotl32(x1,  6); x1 ^= x0;
    x0 += k1; x1 += ks2 + 1u;
    x0 += x1; x1 = rotl32(x1, 17); x1 ^= x0;
    x0 += x1; x1 = rotl32(x1, 29); x1 ^= x0;
    x0 += x1; x1 = rotl32(x1, 16); x1 ^= x0;
    x0 += x1; x1 = rotl32(x1, 24); x1 ^= x0;
    x0 += ks2; x1 += k0 + 2u;
    x0 += x1; x1 = rotl32(x1, 13); x1 ^= x0;
    x0 += x1; x1 = rotl32(x1, 15); x1 ^= x0;
    x0 += x1; x1 = rotl32(x1, 26); x1 ^= x0;
    x0 += x1; x1 = rotl32(x1,  6); x1 ^= x0;
    x0 += k0; x1 += k1 + 3u;
    x0 += x1; x1 = rotl32(x1, 17); x1 ^= x0;
    x0 += x1; x1 = rotl32(x1, 29); x1 ^= x0;
    x0 += x1; x1 = rotl32(x1, 16); x1 ^= x0;
    x0 += x1; x1 = rotl32(x1, 24); x1 ^= x0;
    x0 += k1; x1 += ks2 + 4u;
    x0 += x1; x1 = rotl32(x1, 13); x1 ^= x0;
    x0 += x1; x1 = rotl32(x1, 15); x1 ^= x0;
    x0 += x1; x1 = rotl32(x1, 26); x1 ^= x0;
    x0 += x1; x1 = rotl32(x1,  6); x1 ^= x0;
    x0 += ks2; x1 += k0 + 5u;
    o0 = x0; o1 = x1;
}

__device__ __forceinline__ uint32_t jax_bits32(uint32_t k0, uint32_t k1, uint32_t i) {
    uint32_t o0, o1;
    threefry2x32(k0, k1, 0u, i, o0, o1);
    return o0 ^ o1;
}

// ---------------- tri-GEMM: 64x128 tile, 4x8/thread, split-N cols -----------
// blockIdx.z in {0,1,2} selects (A,W,b,C,K,N). Per-output arithmetic is the
// locked ascending-k single-accumulator FMA chain over BK=16 tiles.
// fusemask bit z: A columns >= concatK come from feat (lda = concatK).
// Thread (tx,ty) owns rows bm+ty*4+i, cols {bn+tx*4+j} and {bn+64+tx*4+j}:
// both W reads are 16B-lane-stride LDS.128 -> conflict-free.
__global__ __launch_bounds__(256) void gemm3_kernel(
    const float* __restrict__ A0, const float* __restrict__ A1, const float* __restrict__ A2,
    const float* __restrict__ W0, const float* __restrict__ W1, const float* __restrict__ W2,
    const float* __restrict__ b0, const float* __restrict__ b1, const float* __restrict__ b2,
    float* __restrict__ C0, float* __restrict__ C1, float* __restrict__ C2,
    int K0, int K1, int K2, int N0, int N1, int N2,
    int actmask, int fusemask,
    const float* __restrict__ feat, int concatK)
{
    __shared__ float As[16][68];     // pad 68: 2-way max on transposed store
    __shared__ float Ws[16][128];

    const int z = blockIdx.z;
    const float* A = (z == 0) ? A0 : (z == 1) ? A1 : A2;
    const float* W = (z == 0) ? W0 : (z == 1) ? W1 : W2;
    const float* bias = (z == 0) ? b0 : (z == 1) ? b1 : b2;
    float* C = (z == 0) ? C0 : (z == 1) ? C1 : C2;
    const int K = (z == 0) ? K0 : (z == 1) ? K1 : K2;
    const int N = (z == 0) ? N0 : (z == 1) ? N1 : N2;
    const bool act  = (actmask >> z) & 1;
    const bool fuse = (fusemask >> z) & 1;
    const int lda = fuse ? concatK : K;

    const int bm = blockIdx.x * 64;
    const int bn = blockIdx.y * 128;
    if (bn >= N) return;             // no-op block (narrow-N z's)

    const int tid = threadIdx.x;
    const int tx = tid & 15;
    const int ty = tid >> 4;

    float acc[4][8];
#pragma unroll
    for (int i = 0; i < 4; i++)
#pragma unroll
        for (int j = 0; j < 8; j++) acc[i][j] = 0.f;

    for (int k0 = 0; k0 < K; k0 += 16) {
        // A tile: 64 rows x 16 k, transposed store As[c][r]
#pragma unroll
        for (int l = 0; l < 4; l++) {
            int e = tid + l * 256;
            int r = e >> 4, c = e & 15;
            int k = k0 + c;
            float v = 0.f;
            if (k < K) {
                if (fuse && k >= concatK)
                    v = feat[(size_t)(bm + r) * FDIM + (k - concatK)];
                else
                    v = A[(size_t)(bm + r) * lda + k];
            }
            As[c][r] = v;
        }
        // W tile: 16 k x 128 cols (coalesced; conflict-free store)
#pragma unroll
        for (int l = 0; l < 8; l++) {
            int e = tid + l * 256;
            int r = e >> 7, c = e & 127;
            int k = k0 + r, col = bn + c;
            float v = 0.f;
            if (k < K && col < N) v = W[(size_t)k * N + col];
            Ws[r][c] = v;
        }
        __syncthreads();
#pragma unroll
        for (int kk = 0; kk < 16; kk++) {
            float4 av  = *reinterpret_cast<const float4*>(&As[kk][ty * 4]);
            float4 wv0 = *reinterpret_cast<const float4*>(&Ws[kk][tx * 4]);
            float4 wv1 = *reinterpret_cast<const float4*>(&Ws[kk][64 + tx * 4]);
            float a_[4] = {av.x, av.y, av.z, av.w};
            float w_[8] = {wv0.x, wv0.y, wv0.z, wv0.w,
                           wv1.x, wv1.y, wv1.z, wv1.w};
#pragma unroll
            for (int i = 0; i < 4; i++)
#pragma unroll
                for (int j = 0; j < 8; j++)
                    acc[i][j] = __fmaf_rn(a_[i], w_[j], acc[i][j]);
        }
        __syncthreads();
    }

    const bool fullN = (bn + 128 <= N);
#pragma unroll
    for (int i = 0; i < 4; i++) {
        int row = bm + ty * 4 + i;
#pragma unroll
        for (int h = 0; h < 2; h++) {       // two column groups
            int colb = bn + h * 64 + tx * 4;
            float v[4];
#pragma unroll
            for (int j = 0; j < 4; j++) {
                float x = acc[i][h * 4 + j];
                int col = colb + j;
                if (col < N) {
                    if (bias) x = __fadd_rn(x, bias[col]);
                    if (act) x = xla_elu(x);
                }
                v[j] = x;
            }
            if (fullN) {
                *reinterpret_cast<float4*>(&C[(size_t)row * N + colb]) =
                    make_float4(v[0], v[1], v[2], v[3]);
            } else {
#pragma unroll
                for (int j = 0; j < 4; j++)
                    if (colb + j < N) C[(size_t)row * N + colb + j] = v[j];
            }
        }
    }
}

// ---------------- x = elu(weighted gather of W_in rows + b_in) -------------
__global__ __launch_bounds__(256) void compute_x_kernel(
    const float* __restrict__ W_in, const float* __restrict__ b_in,
    const int* __restrict__ actions, int t)
{
    int b = blockIdx.x;
    int a = (t == 0) ? 0 : actions[(t - 1) * B + b];
    __shared__ int idx[32];
    __shared__ float wgt[32];
    if (threadIdx.x < 32) {
        idx[threadIdx.x] = (t == 0) ? 0 : g_zidx[b * 32 + threadIdx.x];
        wgt[threadIdx.x] = (t == 0) ? 0.f : g_zw[b * 32 + threadIdx.x];
    }
    __syncthreads();
    for (int j = threadIdx.x; j < MLP; j += blockDim.x) {
        float s = 0.f;
        if (t > 0) {
#pragma unroll
            for (int c = 0; c < 32; c++)
                s = __fmaf_rn(wgt[c], W_in[(size_t)(c * 32 + idx[c]) * MLP + j], s);
        }
        s = __fmaf_rn(1.0f, W_in[(size_t)(ZF + a) * MLP + j], s);
        s = __fadd_rn(s, b_in[j]);
        g_x[b * MLP + j] = xla_elu(s);
    }
}

// ---------------- GRU gate pointwise ----------------------------------------
__global__ __launch_bounds__(256) void gru_kernel()
{
    int i = blockIdx.x * blockDim.x + threadIdx.x;  // [0, B*GRU_H)
    int b = i >> 11, j = i & (GRU_H - 1);
    const float* gib = g_gi + (size_t)b * G3;
    const float* ghb = g_gh + (size_t)b * G3;
    float ir = gib[j],              hr = ghb[j];
    float iz = gib[GRU_H + j],      hz = ghb[GRU_H + j];
    float in_ = gib[2 * GRU_H + j], hn = ghb[2 * GRU_H + j];
    float r  = xla_sigmoid(__fadd_rn(ir, hr));
    float zg = xla_sigmoid(__fadd_rn(iz, hz));
    float n  = xla_tanh(__fmaf_rn(r, hn, in_));
    float hp = g_h[i];
    g_h[i] = __fmaf_rn(zg, hp, __fmul_rn(__fsub_rn(1.0f, zg), n));
}

__global__ __launch_bounds__(256) void zero_h_kernel()
{
    int i = blockIdx.x * blockDim.x + threadIdx.x;
    if (i < B * GRU_H) g_h[i] = 0.f;
}

// ---------------- categorical sample + straight-through weight --------------
__global__ __launch_bounds__(256) void sample_kernel(
    const float* __restrict__ post, int t)
{
    int b = blockIdx.x;
    int warp = threadIdx.x >> 5;
    int lane = threadIdx.x & 31;
    uint32_t k0, k1;
    threefry2x32(0u, 42u, 0u, (uint32_t)t, k0, k1);   // fold_in(key(42), t)

    const float TINY = 1.1754943508222875e-38f;

    for (int c = warp; c < 32; c += 8) {
        float l = post[(size_t)b * ZF + c * 32 + lane];

        uint32_t i = (uint32_t)((b * 32 + c) * 32 + lane);
        uint32_t bits = jax_bits32(k0, k1, i);
        float f = __fadd_rn(__uint_as_float((bits >> 9) | 0x3f800000u), -1.0f);
        float u = fmaxf(TINY, __fadd_rn(f, TINY));
        float g = -xla_log(-xla_log(u));
        float v = __fadd_rn(l, g);

        float bv = v; int bi = lane;
#pragma unroll
        for (int off = 16; off > 0; off >>= 1) {
            float ov = __shfl_down_sync(0xffffffffu, bv, off);
            int   oi = __shfl_down_sync(0xffffffffu, bi, off);
            if (ov > bv || (ov == bv && oi < bi)) { bv = ov; bi = oi; }
        }
        bi = __shfl_sync(0xffffffffu, bi, 0);

        float m = l;
#pragma unroll
        for (int off = 16; off > 0; off >>= 1)
            m = fmaxf(m, __shfl_xor_sync(0xffffffffu, m, off));
        float e = xla_exp(__fadd_rn(l, -m));
        float s = 0.f;
#pragma unroll
        for (int ll = 0; ll < 32; ll++)
            s = __fadd_rn(s, __shfl_sync(0xffffffffu, e, ll));
        float p = __fdiv_rn(e, s);
        float psel = __shfl_sync(0xffffffffu, p, bi);
        if (lane == 0) {
            float w = __fadd_rn(__fadd_rn(1.0f, psel), -psel);  // fl(1+p)-p
            g_zidx[b * 32 + c] = bi;
            g_zw[b * 32 + c] = w;
        }
    }
}

// ---------------------------------------------------------------------------
extern "C" void kernel_launch(void* const* d_in, const int* in_sizes, int n_in,
                              void* d_out, int out_size)
{
    const float* features = (const float*)d_in[0];   // [64,256,1024]
    const int*   actions  = (const int*)  d_in[1];   // [64,256]
    const float* W_in = (const float*)d_in[2];       // [1030,1000]
    const float* b_in = (const float*)d_in[3];
    const float* W_ih = (const float*)d_in[4];       // [1000,6144]
    const float* W_hh = (const float*)d_in[5];       // [2048,6144]
    const float* b_ih = (const float*)d_in[6];
    const float* b_hh = (const float*)d_in[7];
    const float* Wp1  = (const float*)d_in[8];       // [2048,1000]
    const float* bp1  = (const float*)d_in[9];
    const float* Wp2  = (const float*)d_in[10];      // [1000,1024]
    const float* bp2  = (const float*)d_in[11];
    const float* Wq1  = (const float*)d_in[12];      // [3072,1000]
    const float* bq1  = (const float*)d_in[13];
    const float* Wq2  = (const float*)d_in[14];      // [1000,1024]
    const float* bq2  = (const float*)d_in[15];
    float* out = (float*)d_out;                      // [2,64,256,32,32]

    float *px, *pgi, *pgh, *ph, *pp1, *pq1;
    cudaGetSymbolAddress((void**)&px,  g_x);
    cudaGetSymbolAddress((void**)&pgi, g_gi);
    cudaGetSymbolAddress((void**)&pgh, g_gh);
    cudaGetSymbolAddress((void**)&ph,  g_h);
    cudaGetSymbolAddress((void**)&pp1, g_p1);
    cudaGetSymbolAddress((void**)&pq1, g_q1);

    // ---- prologue: h = 0; x_0; gi_0 | gh_0 (pair launch) ----
    zero_h_kernel<<<(B * GRU_H + 255) / 256, 256>>>();
    compute_x_kernel<<<B, 256>>>(W_in, b_in, actions, 0);
    gemm3_kernel<<<dim3(B / 64, G3 / 128, 2), 256>>>(
        px, ph, nullptr,  W_ih, W_hh, nullptr,  b_ih, b_hh, nullptr,
        pgi, pgh, nullptr,  MLP, GRU_H, 0,  G3, G3, 0,
        /*act*/0, /*fuse*/0, nullptr, 0);

    for (int t = 0; t < T_STEPS; t++) {
        const float* feat_t = features + (size_t)t * B * FDIM;
        float* out_prior = out + (size_t)t * B * ZF;
        float* out_post  = out + ((size_t)(T_STEPS + t)) * B * ZF;

        // h_t = gru(gi_t, gh_t, h_{t-1})
        gru_kernel<<<(B * GRU_H) / 256, 256>>>();

        // triple: gh_{t+1} | p1_t | q1_t   (all depend only on h_t / feat)
        gemm3_kernel<<<dim3(B / 64, G3 / 128, 3), 256>>>(
            ph, ph, ph,  W_hh, Wp1, Wq1,  b_hh, bp1, bq1,
            pgh, pp1, pq1,  GRU_H, GRU_H, GRU_H + FDIM,
            G3, MLP, MLP,
            /*act*/0b110, /*fuse*/0b100, feat_t, GRU_H);

        // pair: prior_t | post_t
        gemm3_kernel<<<dim3(B / 64, ZF / 128, 2), 256>>>(
            pp1, pq1, nullptr,  Wp2, Wq2, nullptr,  bp2, bq2, nullptr,
            out_prior, out_post, nullptr,  MLP, MLP, 0,  ZF, ZF, 0,
            /*act*/0, /*fuse*/0, nullptr, 0);

        // sample z_t (feeds x_{t+1})
        sample_kernel<<<B, 256>>>(out_post, t);

        if (t < T_STEPS - 1) {
            compute_x_kernel<<<B, 256>>>(W_in, b_in, actions, t + 1);
            gemm3_kernel<<<dim3(B / 64, G3 / 128, 1), 256>>>(
                px, nullptr, nullptr,  W_ih, nullptr, nullptr,
                b_ih, nullptr, nullptr,  pgi, nullptr, nullptr,
                MLP, 0, 0,  G3, 0, 0,
                /*act*/0, /*fuse*/0, nullptr, 0);
        }
    }
}

// round 11
// speedup vs baseline: 2.6202x; 1.5926x over previous
#include <cuda_runtime.h>
#include <cstdint>

// ---------------------------------------------------------------------------
// RSSMCore: T=64 sequential steps, B=256.  PASSING MODEL (locked since R6):
//  * RNG: jax_threefry_partitionable: bits(i) = o0^o1 of threefry(key,(0,i)).
//  * GEMM: exact f32, per-output ascending-k single-accumulator FMA chain
//    (BK=16 tiles ascending) — flip-free at rel_err 9.051719e-07.
//    Per-output arithmetic MUST NOT change (scheduling/prefetch may).
//  * z weights w = fl(1+p)-p carried into the W_in gather.
//  * XLA rational tanh / logistic / cephes exp/log, FMA-form.
// R10 kept: 64x128 tile 4x8/thread conflict-free split-N; triple-merge.
// Round 11 (perf only):
//  * gemm3 DOUBLE-BUFFERED: ping-pong smem + register-staged float4 prefetch
//    of tile t+1 behind tile t's FMAs; one __syncthreads per tile (was 2 +
//    exposed ~250cyc L2 latency per tile -> the measured 2.2x-off-roofline).
//  * t=63: no gh_{64} (wasted 6.4 GF), no sample.
//  * sample+x fused into one kernel (smem handoff of zidx/zw).
//  * gru vectorized float4.
// ---------------------------------------------------------------------------

#define T_STEPS 64
#define B 256
#define GRU_H 2048
#define MLP 1000
#define ZF 1024
#define FDIM 1024
#define G3 (3 * GRU_H)   // 6144

// ---------------- scratch (device globals; no allocation allowed) ----------
__device__ float g_x[B * MLP];
__device__ float g_gi[B * G3];
__device__ float g_gh[B * G3];
__device__ float g_h[B * GRU_H];
__device__ float g_p1[B * MLP];
__device__ float g_q1[B * MLP];

// =================== XLA-matched elementwise math (FMA form) ================

__device__ __forceinline__ float xla_tanh(float x) {
    if (fabsf(x) < 0.0004f) return x;
    float xc = fminf(fmaxf(x, -7.90531110763549805f), 7.90531110763549805f);
    float x2 = __fmul_rn(xc, xc);
    float p = -2.76076847742355e-16f;
    p = __fmaf_rn(p, x2, 2.00018790482477e-13f);
    p = __fmaf_rn(p, x2, -8.60467152213735e-11f);
    p = __fmaf_rn(p, x2, 5.12229709037114e-08f);
    p = __fmaf_rn(p, x2, 1.48572235717979e-05f);
    p = __fmaf_rn(p, x2, 6.37261928875436e-04f);
    p = __fmaf_rn(p, x2, 4.89352455891786e-03f);
    p = __fmul_rn(p, xc);
    float q = 1.19825839466702e-06f;
    q = __fmaf_rn(q, x2, 1.18534705686654e-04f);
    q = __fmaf_rn(q, x2, 2.26843463243900e-03f);
    q = __fmaf_rn(q, x2, 4.89352518554385e-03f);
    return __fdiv_rn(p, q);
}

__device__ __forceinline__ float xla_sigmoid(float x) {
    return __fmaf_rn(0.5f, xla_tanh(__fmul_rn(0.5f, x)), 0.5f);
}

__device__ __forceinline__ float xla_log(float a) {
    int ix = __float_as_int(a);
    float e = (float)((ix >> 23) - 126);
    float m = __int_as_float((ix & 0x007fffff) | 0x3f000000);
    if (m < 0.707106781186547524f) { e = __fadd_rn(e, -1.0f); m = __fadd_rn(m, m); }
    m = __fadd_rn(m, -1.0f);
    float z = __fmul_rn(m, m);
    float y = 7.0376836292e-2f;
    y = __fmaf_rn(y, m, -1.1514610310e-1f);
    y = __fmaf_rn(y, m, 1.1676998740e-1f);
    y = __fmaf_rn(y, m, -1.2420140846e-1f);
    y = __fmaf_rn(y, m, 1.4249322787e-1f);
    y = __fmaf_rn(y, m, -1.6668057665e-1f);
    y = __fmaf_rn(y, m, 2.0000714765e-1f);
    y = __fmaf_rn(y, m, -2.4999993993e-1f);
    y = __fmaf_rn(y, m, 3.3333331174e-1f);
    y = __fmul_rn(__fmul_rn(y, m), z);
    y = __fmaf_rn(e, -2.12194440e-4f, y);
    y = __fmaf_rn(z, -0.5f, y);
    float r = __fadd_rn(m, y);
    r = __fmaf_rn(e, 0.693359375f, r);
    return r;
}

__device__ __forceinline__ float xla_exp(float x) {
    float xc = fminf(fmaxf(x, -87.33654f), 88.72283f);
    float m = floorf(__fmaf_rn(xc, 1.44269504088896341f, 0.5f));
    float r = __fmaf_rn(m, -0.693359375f, xc);
    r = __fmaf_rn(m, 2.12194440e-4f, r);
    float r2 = __fmul_rn(r, r);
    float p = 1.9875691500e-4f;
    p = __fmaf_rn(p, r, 1.3981999507e-3f);
    p = __fmaf_rn(p, r, 8.3334519073e-3f);
    p = __fmaf_rn(p, r, 4.1665795894e-2f);
    p = __fmaf_rn(p, r, 1.6666665459e-1f);
    p = __fmaf_rn(p, r, 5.0000001201e-1f);
    float y = __fadd_rn(__fmaf_rn(p, r2, r), 1.0f);
    return __fmul_rn(y, __int_as_float(((int)m + 127) << 23));
}

__device__ __forceinline__ float xla_expm1(float x) {
    if (fabsf(x) < 1e-5f) return __fmaf_rn(__fmul_rn(0.5f, x), x, x);
    return __fadd_rn(xla_exp(x), -1.0f);
}

__device__ __forceinline__ float xla_elu(float x) {
    return (x > 0.0f) ? x : xla_expm1(x);
}

// ---------------- threefry2x32 (JAX bit-exact) ------------------------------
__device__ __forceinline__ uint32_t rotl32(uint32_t v, int r) {
    return (v << r) | (v >> (32 - r));
}

__device__ __forceinline__ void threefry2x32(uint32_t k0, uint32_t k1,
                                             uint32_t x0, uint32_t x1,
                                             uint32_t& o0, uint32_t& o1) {
    uint32_t ks2 = k0 ^ k1 ^ 0x1BD11BDAu;
    x0 += k0; x1 += k1;
    x0 += x1; x1 = rotl32(x1, 13); x1 ^= x0;
    x0 += x1; x1 = rotl32(x1, 15); x1 ^= x0;
    x0 += x1; x1 = rotl32(x1, 26); x1 ^= x0;
    x0 += x1; x1 = rotl32(x1,  6); x1 ^= x0;
    x0 += k1; x1 += ks2 + 1u;
    x0 += x1; x1 = rotl32(x1, 17); x1 ^= x0;
    x0 += x1; x1 = rotl32(x1, 29); x1 ^= x0;
    x0 += x1; x1 = rotl32(x1, 16); x1 ^= x0;
    x0 += x1; x1 = rotl32(x1, 24); x1 ^= x0;
    x0 += ks2; x1 += k0 + 2u;
    x0 += x1; x1 = rotl32(x1, 13); x1 ^= x0;
    x0 += x1; x1 = rotl32(x1, 15); x1 ^= x0;
    x0 += x1; x1 = rotl32(x1, 26); x1 ^= x0;
    x0 += x1; x1 = rotl32(x1,  6); x1 ^= x0;
    x0 += k0; x1 += k1 + 3u;
    x0 += x1; x1 = rotl32(x1, 17); x1 ^= x0;
    x0 += x1; x1 = rotl32(x1, 29); x1 ^= x0;
    x0 += x1; x1 = rotl32(x1, 16); x1 ^= x0;
    x0 += x1; x1 = rotl32(x1, 24); x1 ^= x0;
    x0 += k1; x1 += ks2 + 4u;
    x0 += x1; x1 = rotl32(x1, 13); x1 ^= x0;
    x0 += x1; x1 = rotl32(x1, 15); x1 ^= x0;
    x0 += x1; x1 = rotl32(x1, 26); x1 ^= x0;
    x0 += x1; x1 = rotl32(x1,  6); x1 ^= x0;
    x0 += ks2; x1 += k0 + 5u;
    o0 = x0; o1 = x1;
}

__device__ __forceinline__ uint32_t jax_bits32(uint32_t k0, uint32_t k1, uint32_t i) {
    uint32_t o0, o1;
    threefry2x32(k0, k1, 0u, i, o0, o1);
    return o0 ^ o1;
}

// ---------------- guarded float4 load (per-element bounds) ------------------
__device__ __forceinline__ float4 load_f4_guard(const float* __restrict__ src,
                                                size_t base, int k, int Klim) {
    if (k + 3 < Klim) return *reinterpret_cast<const float4*>(&src[base]);
    float4 v;
    v.x = (k + 0 < Klim) ? src[base + 0] : 0.f;
    v.y = (k + 1 < Klim) ? src[base + 1] : 0.f;
    v.z = (k + 2 < Klim) ? src[base + 2] : 0.f;
    v.w = (k + 3 < Klim) ? src[base + 3] : 0.f;
    return v;
}

// ---------------- tri-GEMM: 64x128, 4x8/thread, DOUBLE-BUFFERED -------------
// blockIdx.z selects (A,W,b,C,K,N). Per-output arithmetic: locked ascending-k
// single-accumulator FMA chain over BK=16 tiles (identical to R6/R8/R10).
// Ping-pong smem; tile t+1 prefetched into registers behind tile t's FMAs.
__global__ __launch_bounds__(256) void gemm3_kernel(
    const float* __restrict__ A0, const float* __restrict__ A1, const float* __restrict__ A2,
    const float* __restrict__ W0, const float* __restrict__ W1, const float* __restrict__ W2,
    const float* __restrict__ b0, const float* __restrict__ b1, const float* __restrict__ b2,
    float* __restrict__ C0, float* __restrict__ C1, float* __restrict__ C2,
    int K0, int K1, int K2, int N0, int N1, int N2,
    int actmask, int fusemask,
    const float* __restrict__ feat, int concatK)
{
    __shared__ float As[2][16][68];    // padded: 2-way max on transposed store
    __shared__ float Ws[2][16][128];

    const int z = blockIdx.z;
    const float* A = (z == 0) ? A0 : (z == 1) ? A1 : A2;
    const float* W = (z == 0) ? W0 : (z == 1) ? W1 : W2;
    const float* bias = (z == 0) ? b0 : (z == 1) ? b1 : b2;
    float* C = (z == 0) ? C0 : (z == 1) ? C1 : C2;
    const int K = (z == 0) ? K0 : (z == 1) ? K1 : K2;
    const int N = (z == 0) ? N0 : (z == 1) ? N1 : N2;
    const bool act  = (actmask >> z) & 1;
    const bool fuse = (fusemask >> z) & 1;
    const int lda = fuse ? concatK : K;

    const int bm = blockIdx.x * 64;
    const int bn = blockIdx.y * 128;
    if (bn >= N) return;               // no-op block (narrow-N z's)

    const int tid = threadIdx.x;
    const int tx = tid & 15;
    const int ty = tid >> 4;
    // A staging: thread -> (row, 4 consecutive k)
    const int arow = tid >> 2, ac4 = tid & 3;
    // W staging: 2 x float4; rows wrow and wrow+8, cols wcol4*4..+3
    const int wrow = tid >> 5, wcol4 = tid & 31;

    float acc[4][8];
#pragma unroll
    for (int i = 0; i < 4; i++)
#pragma unroll
        for (int j = 0; j < 8; j++) acc[i][j] = 0.f;

    const int ntiles = (K + 15) >> 4;

    // ---- tile loader into registers (float4, guarded tails) ----
    float4 aR, wR0, wR1;
    auto load_tile = [&](int k0) {
        int ka = k0 + ac4 * 4;
        if (fuse && ka >= concatK)
            aR = load_f4_guard(feat, (size_t)(bm + arow) * FDIM + (ka - concatK), ka, K);
        else
            aR = load_f4_guard(A, (size_t)(bm + arow) * lda + ka, ka, K);

        int kw0 = k0 + wrow, kw1 = k0 + wrow + 8;
        int col = bn + wcol4 * 4;
        if (kw0 < K) {
            if (col + 3 < N) wR0 = *reinterpret_cast<const float4*>(&W[(size_t)kw0 * N + col]);
            else wR0 = load_f4_guard(W, (size_t)kw0 * N + col, col, N);
        } else wR0 = make_float4(0.f, 0.f, 0.f, 0.f);
        if (kw1 < K) {
            if (col + 3 < N) wR1 = *reinterpret_cast<const float4*>(&W[(size_t)kw1 * N + col]);
            else wR1 = load_f4_guard(W, (size_t)kw1 * N + col, col, N);
        } else wR1 = make_float4(0.f, 0.f, 0.f, 0.f);
    };
    auto store_tile = [&](int buf) {
        As[buf][ac4 * 4 + 0][arow] = aR.x;
        As[buf][ac4 * 4 + 1][arow] = aR.y;
        As[buf][ac4 * 4 + 2][arow] = aR.z;
        As[buf][ac4 * 4 + 3][arow] = aR.w;
        *reinterpret_cast<float4*>(&Ws[buf][wrow][wcol4 * 4]) = wR0;
        *reinterpret_cast<float4*>(&Ws[buf][wrow + 8][wcol4 * 4]) = wR1;
    };

    load_tile(0);
    store_tile(0);
    __syncthreads();

    int buf = 0;
    for (int tI = 0; tI < ntiles; tI++) {
        const bool more = (tI + 1 < ntiles);
        if (more) load_tile((tI + 1) << 4);   // prefetch behind the FMAs below

#pragma unroll
        for (int kk = 0; kk < 16; kk++) {
            float4 av  = *reinterpret_cast<const float4*>(&As[buf][kk][ty * 4]);
            float4 wv0 = *reinterpret_cast<const float4*>(&Ws[buf][kk][tx * 4]);
            float4 wv1 = *reinterpret_cast<const float4*>(&Ws[buf][kk][64 + tx * 4]);
            float a_[4] = {av.x, av.y, av.z, av.w};
            float w_[8] = {wv0.x, wv0.y, wv0.z, wv0.w,
                           wv1.x, wv1.y, wv1.z, wv1.w};
#pragma unroll
            for (int i = 0; i < 4; i++)
#pragma unroll
                for (int j = 0; j < 8; j++)
                    acc[i][j] = __fmaf_rn(a_[i], w_[j], acc[i][j]);
        }
        if (more) {
            store_tile(buf ^ 1);     // other buffer: no reader, no pre-sync
            __syncthreads();         // publish before next iteration's reads
            buf ^= 1;
        }
    }

    const bool fullN = (bn + 128 <= N);
#pragma unroll
    for (int i = 0; i < 4; i++) {
        int row = bm + ty * 4 + i;
#pragma unroll
        for (int h = 0; h < 2; h++) {
            int colb = bn + h * 64 + tx * 4;
            float v[4];
#pragma unroll
            for (int j = 0; j < 4; j++) {
                float x = acc[i][h * 4 + j];
                int col = colb + j;
                if (col < N) {
                    if (bias) x = __fadd_rn(x, bias[col]);
                    if (act) x = xla_elu(x);
                }
                v[j] = x;
            }
            if (fullN) {
                *reinterpret_cast<float4*>(&C[(size_t)row * N + colb]) =
                    make_float4(v[0], v[1], v[2], v[3]);
            } else {
#pragma unroll
                for (int j = 0; j < 4; j++)
                    if (colb + j < N) C[(size_t)row * N + colb + j] = v[j];
            }
        }
    }
}

// ---------------- x_0 = elu(W_in action row + b_in) (prologue only) --------
__global__ __launch_bounds__(256) void compute_x0_kernel(
    const float* __restrict__ W_in, const float* __restrict__ b_in)
{
    int b = blockIdx.x;
    for (int j = threadIdx.x; j < MLP; j += blockDim.x) {
        float s = W_in[(size_t)ZF * MLP + j];   // action 0 row, weight 1
        s = __fadd_rn(s, b_in[j]);
        g_x[b * MLP + j] = xla_elu(s);
    }
}

// ---------------- GRU gate pointwise (float4) -------------------------------
__global__ __launch_bounds__(256) void gru_kernel()
{
    int i4 = blockIdx.x * blockDim.x + threadIdx.x;   // [0, B*GRU_H/4)
    int b = i4 >> 9;                                  // 512 float4 per batch
    int j4 = i4 & 511;
    const float4* gib = reinterpret_cast<const float4*>(g_gi + (size_t)b * G3);
    const float4* ghb = reinterpret_cast<const float4*>(g_gh + (size_t)b * G3);
    float4 ir4 = gib[j4],        hr4 = ghb[j4];
    float4 iz4 = gib[512 + j4],  hz4 = ghb[512 + j4];
    float4 in4 = gib[1024 + j4], hn4 = ghb[1024 + j4];
    float4 hp4 = reinterpret_cast<const float4*>(g_h)[i4];
    float4 o;
    {
        float r  = xla_sigmoid(__fadd_rn(ir4.x, hr4.x));
        float zg = xla_sigmoid(__fadd_rn(iz4.x, hz4.x));
        float n  = xla_tanh(__fmaf_rn(r, hn4.x, in4.x));
        o.x = __fmaf_rn(zg, hp4.x, __fmul_rn(__fsub_rn(1.0f, zg), n));
    }
    {
        float r  = xla_sigmoid(__fadd_rn(ir4.y, hr4.y));
        float zg = xla_sigmoid(__fadd_rn(iz4.y, hz4.y));
        float n  = xla_tanh(__fmaf_rn(r, hn4.y, in4.y));
        o.y = __fmaf_rn(zg, hp4.y, __fmul_rn(__fsub_rn(1.0f, zg), n));
    }
    {
        float r  = xla_sigmoid(__fadd_rn(ir4.z, hr4.z));
        float zg = xla_sigmoid(__fadd_rn(iz4.z, hz4.z));
        float n  = xla_tanh(__fmaf_rn(r, hn4.z, in4.z));
        o.z = __fmaf_rn(zg, hp4.z, __fmul_rn(__fsub_rn(1.0f, zg), n));
    }
    {
        float r  = xla_sigmoid(__fadd_rn(ir4.w, hr4.w));
        float zg = xla_sigmoid(__fadd_rn(iz4.w, hz4.w));
        float n  = xla_tanh(__fmaf_rn(r, hn4.w, in4.w));
        o.w = __fmaf_rn(zg, hp4.w, __fmul_rn(__fsub_rn(1.0f, zg), n));
    }
    reinterpret_cast<float4*>(g_h)[i4] = o;
}

__global__ __launch_bounds__(256) void zero_h_kernel()
{
    int i = blockIdx.x * blockDim.x + threadIdx.x;
    if (i < B * GRU_H) g_h[i] = 0.f;
}

// ---------------- fused: sample z_t  +  x_{t+1} ------------------------------
// Block b: (1) bit-exact jax.random.categorical for step t + straight-through
// weight w = fl(1+p)-p into smem; (2) x_{t+1} = elu(weighted W_in gather).
__global__ __launch_bounds__(256) void sample_x_kernel(
    const float* __restrict__ post, int t,
    const float* __restrict__ W_in, const float* __restrict__ b_in,
    const int* __restrict__ actions)
{
    __shared__ int   idx[32];
    __shared__ float wgt[32];

    int b = blockIdx.x;
    int warp = threadIdx.x >> 5;
    int lane = threadIdx.x & 31;
    uint32_t k0, k1;
    threefry2x32(0u, 42u, 0u, (uint32_t)t, k0, k1);   // fold_in(key(42), t)

    const float TINY = 1.1754943508222875e-38f;

    for (int c = warp; c < 32; c += 8) {
        float l = post[(size_t)b * ZF + c * 32 + lane];

        uint32_t i = (uint32_t)((b * 32 + c) * 32 + lane);
        uint32_t bits = jax_bits32(k0, k1, i);
        float f = __fadd_rn(__uint_as_float((bits >> 9) | 0x3f800000u), -1.0f);
        float u = fmaxf(TINY, __fadd_rn(f, TINY));
        float g = -xla_log(-xla_log(u));
        float v = __fadd_rn(l, g);

        float bv = v; int bi = lane;
#pragma unroll
        for (int off = 16; off > 0; off >>= 1) {
            float ov = __shfl_down_sync(0xffffffffu, bv, off);
            int   oi = __shfl_down_sync(0xffffffffu, bi, off);
            if (ov > bv || (ov == bv && oi < bi)) { bv = ov; bi = oi; }
        }
        bi = __shfl_sync(0xffffffffu, bi, 0);

        float m = l;
#pragma unroll
        for (int off = 16; off > 0; off >>= 1)
            m = fmaxf(m, __shfl_xor_sync(0xffffffffu, m, off));
        float e = xla_exp(__fadd_rn(l, -m));
        float s = 0.f;
#pragma unroll
        for (int ll = 0; ll < 32; ll++)
            s = __fadd_rn(s, __shfl_sync(0xffffffffu, e, ll));
        float p = __fdiv_rn(e, s);
        float psel = __shfl_sync(0xffffffffu, p, bi);
        if (lane == 0) {
            idx[c] = bi;
            wgt[c] = __fadd_rn(__fadd_rn(1.0f, psel), -psel);   // fl(1+p)-p
        }
    }
    __syncthreads();

    // x_{t+1}: ascending-k chain over nonzeros (cats 0..31, action row, bias)
    int a = actions[t * B + b];                        // act_seq[t+1] = actions[t]
    for (int j = threadIdx.x; j < MLP; j += blockDim.x) {
        float s = 0.f;
#pragma unroll
        for (int c = 0; c < 32; c++)
            s = __fmaf_rn(wgt[c], W_in[(size_t)(c * 32 + idx[c]) * MLP + j], s);
        s = __fmaf_rn(1.0f, W_in[(size_t)(ZF + a) * MLP + j], s);
        s = __fadd_rn(s, b_in[j]);
        g_x[b * MLP + j] = xla_elu(s);
    }
}

// ---------------------------------------------------------------------------
extern "C" void kernel_launch(void* const* d_in, const int* in_sizes, int n_in,
                              void* d_out, int out_size)
{
    const float* features = (const float*)d_in[0];   // [64,256,1024]
    const int*   actions  = (const int*)  d_in[1];   // [64,256]
    const float* W_in = (const float*)d_in[2];       // [1030,1000]
    const float* b_in = (const float*)d_in[3];
    const float* W_ih = (const float*)d_in[4];       // [1000,6144]
    const float* W_hh = (const float*)d_in[5];       // [2048,6144]
    const float* b_ih = (const float*)d_in[6];
    const float* b_hh = (const float*)d_in[7];
    const float* Wp1  = (const float*)d_in[8];       // [2048,1000]
    const float* bp1  = (const float*)d_in[9];
    const float* Wp2  = (const float*)d_in[10];      // [1000,1024]
    const float* bp2  = (const float*)d_in[11];
    const float* Wq1  = (const float*)d_in[12];      // [3072,1000]
    const float* bq1  = (const float*)d_in[13];
    const float* Wq2  = (const float*)d_in[14];      // [1000,1024]
    const float* bq2  = (const float*)d_in[15];
    float* out = (float*)d_out;                      // [2,64,256,32,32]

    float *px, *pgi, *pgh, *ph, *pp1, *pq1;
    cudaGetSymbolAddress((void**)&px,  g_x);
    cudaGetSymbolAddress((void**)&pgi, g_gi);
    cudaGetSymbolAddress((void**)&pgh, g_gh);
    cudaGetSymbolAddress((void**)&ph,  g_h);
    cudaGetSymbolAddress((void**)&pp1, g_p1);
    cudaGetSymbolAddress((void**)&pq1, g_q1);

    // ---- prologue: h = 0; x_0; [gi_0 | gh_0] ----
    zero_h_kernel<<<(B * GRU_H + 255) / 256, 256>>>();
    compute_x0_kernel<<<B, 256>>>(W_in, b_in);
    gemm3_kernel<<<dim3(B / 64, G3 / 128, 2), 256>>>(
        px, ph, nullptr,  W_ih, W_hh, nullptr,  b_ih, b_hh, nullptr,
        pgi, pgh, nullptr,  MLP, GRU_H, 0,  G3, G3, 0,
        /*act*/0, /*fuse*/0, nullptr, 0);

    for (int t = 0; t < T_STEPS; t++) {
        const float* feat_t = features + (size_t)t * B * FDIM;
        float* out_prior = out + (size_t)t * B * ZF;
        float* out_post  = out + ((size_t)(T_STEPS + t)) * B * ZF;

        // h_t = gru(gi_t, gh_t, h_{t-1})
        gru_kernel<<<(B * GRU_H / 4) / 256, 256>>>();

        if (t < T_STEPS - 1) {
            // triple: gh_{t+1} | p1_t | q1_t   (all depend only on h_t / feat)
            gemm3_kernel<<<dim3(B / 64, G3 / 128, 3), 256>>>(
                ph, ph, ph,  W_hh, Wp1, Wq1,  b_hh, bp1, bq1,
                pgh, pp1, pq1,  GRU_H, GRU_H, GRU_H + FDIM,
                G3, MLP, MLP,
                /*act*/0b110, /*fuse*/0b100, feat_t, GRU_H);
        } else {
            // last step: no gh_{64}
            gemm3_kernel<<<dim3(B / 64, (MLP + 127) / 128, 2), 256>>>(
                ph, ph, nullptr,  Wp1, Wq1, nullptr,  bp1, bq1, nullptr,
                pp1, pq1, nullptr,  GRU_H, GRU_H + FDIM, 0,  MLP, MLP, 0,
                /*act*/0b11, /*fuse*/0b10, feat_t, GRU_H);
        }

        // pair: prior_t | post_t
        gemm3_kernel<<<dim3(B / 64, ZF / 128, 2), 256>>>(
            pp1, pq1, nullptr,  Wp2, Wq2, nullptr,  bp2, bq2, nullptr,
            out_prior, out_post, nullptr,  MLP, MLP, 0,  ZF, ZF, 0,
            /*act*/0, /*fuse*/0, nullptr, 0);

        if (t < T_STEPS - 1) {
            // fused: sample z_t + x_{t+1}, then gi_{t+1}
            sample_x_kernel<<<B, 256>>>(out_post, t, W_in, b_in, actions);
            gemm3_kernel<<<dim3(B / 64, G3 / 128, 1), 256>>>(
                px, nullptr, nullptr,  W_ih, nullptr, nullptr,
                b_ih, nullptr, nullptr,  pgi, nullptr, nullptr,
                MLP, 0, 0,  G3, 0, 0,
                /*act*/0, /*fuse*/0, nullptr, 0);
        }
    }
}

// round 12
// speedup vs baseline: 2.7723x; 1.0580x over previous
#include <cuda_runtime.h>
#include <cstdint>

// ---------------------------------------------------------------------------
// RSSMCore: T=64 sequential steps, B=256.  PASSING MODEL (locked since R6):
//  * RNG: jax_threefry_partitionable: bits(i) = o0^o1 of threefry(key,(0,i)).
//  * GEMM: exact f32, per-output ascending-k single-accumulator FMA chain
//    (BK=16 tiles ascending) — flip-free at rel_err 9.051719e-07.
//    Per-output arithmetic MUST NOT change (scheduling may).
//  * z weights w = fl(1+p)-p carried into the W_in gather.
//  * XLA rational tanh / logistic / cephes exp/log, FMA-form.
// R11 kept: 64x128 4x8 double-buffered conflict-free GEMM core.
// Round 12 (perf only): SINGLE-LAUNCH SOFTWARE PIPELINE per step.
//  One kernel, grid (4,48,7); blockIdx.z = role in dependency order:
//   z0 q1 | z1 gh_{t+1} | z2 p1 | z3 post(wait q1) | z4 prior(wait p1)
//   z5 sample+x_{t+1}(wait post) | z6 gi_{t+1}(wait x)
//  Cross-role sync: per-step atomic counters + threadfence (release/acquire).
//  Consumers overlap with the gh bulk instead of serializing behind it.
//  Deadlock-free: CTA dispatch is monotone in linear block id; wait graph
//  follows id order. Counters reset each execution (replay-deterministic).
// ---------------------------------------------------------------------------

#define T_STEPS 64
#define B 256
#define GRU_H 2048
#define MLP 1000
#define ZF 1024
#define FDIM 1024
#define G3 (3 * GRU_H)   // 6144

// ---------------- scratch (device globals; no allocation allowed) ----------
__device__ float g_x[B * MLP];
__device__ float g_gi[B * G3];
__device__ float g_gh[B * G3];
__device__ float g_h[B * GRU_H];
__device__ float g_p1[B * MLP];
__device__ float g_q1[B * MLP];
__device__ int   g_cnt[T_STEPS][4];   // 0:q1 1:p1 2:post 3:x

// =================== XLA-matched elementwise math (FMA form) ================

__device__ __forceinline__ float xla_tanh(float x) {
    if (fabsf(x) < 0.0004f) return x;
    float xc = fminf(fmaxf(x, -7.90531110763549805f), 7.90531110763549805f);
    float x2 = __fmul_rn(xc, xc);
    float p = -2.76076847742355e-16f;
    p = __fmaf_rn(p, x2, 2.00018790482477e-13f);
    p = __fmaf_rn(p, x2, -8.60467152213735e-11f);
    p = __fmaf_rn(p, x2, 5.12229709037114e-08f);
    p = __fmaf_rn(p, x2, 1.48572235717979e-05f);
    p = __fmaf_rn(p, x2, 6.37261928875436e-04f);
    p = __fmaf_rn(p, x2, 4.89352455891786e-03f);
    p = __fmul_rn(p, xc);
    float q = 1.19825839466702e-06f;
    q = __fmaf_rn(q, x2, 1.18534705686654e-04f);
    q = __fmaf_rn(q, x2, 2.26843463243900e-03f);
    q = __fmaf_rn(q, x2, 4.89352518554385e-03f);
    return __fdiv_rn(p, q);
}

__device__ __forceinline__ float xla_sigmoid(float x) {
    return __fmaf_rn(0.5f, xla_tanh(__fmul_rn(0.5f, x)), 0.5f);
}

__device__ __forceinline__ float xla_log(float a) {
    int ix = __float_as_int(a);
    float e = (float)((ix >> 23) - 126);
    float m = __int_as_float((ix & 0x007fffff) | 0x3f000000);
    if (m < 0.707106781186547524f) { e = __fadd_rn(e, -1.0f); m = __fadd_rn(m, m); }
    m = __fadd_rn(m, -1.0f);
    float z = __fmul_rn(m, m);
    float y = 7.0376836292e-2f;
    y = __fmaf_rn(y, m, -1.1514610310e-1f);
    y = __fmaf_rn(y, m, 1.1676998740e-1f);
    y = __fmaf_rn(y, m, -1.2420140846e-1f);
    y = __fmaf_rn(y, m, 1.4249322787e-1f);
    y = __fmaf_rn(y, m, -1.6668057665e-1f);
    y = __fmaf_rn(y, m, 2.0000714765e-1f);
    y = __fmaf_rn(y, m, -2.4999993993e-1f);
    y = __fmaf_rn(y, m, 3.3333331174e-1f);
    y = __fmul_rn(__fmul_rn(y, m), z);
    y = __fmaf_rn(e, -2.12194440e-4f, y);
    y = __fmaf_rn(z, -0.5f, y);
    float r = __fadd_rn(m, y);
    r = __fmaf_rn(e, 0.693359375f, r);
    return r;
}

__device__ __forceinline__ float xla_exp(float x) {
    float xc = fminf(fmaxf(x, -87.33654f), 88.72283f);
    float m = floorf(__fmaf_rn(xc, 1.44269504088896341f, 0.5f));
    float r = __fmaf_rn(m, -0.693359375f, xc);
    r = __fmaf_rn(m, 2.12194440e-4f, r);
    float r2 = __fmul_rn(r, r);
    float p = 1.9875691500e-4f;
    p = __fmaf_rn(p, r, 1.3981999507e-3f);
    p = __fmaf_rn(p, r, 8.3334519073e-3f);
    p = __fmaf_rn(p, r, 4.1665795894e-2f);
    p = __fmaf_rn(p, r, 1.6666665459e-1f);
    p = __fmaf_rn(p, r, 5.0000001201e-1f);
    float y = __fadd_rn(__fmaf_rn(p, r2, r), 1.0f);
    return __fmul_rn(y, __int_as_float(((int)m + 127) << 23));
}

__device__ __forceinline__ float xla_expm1(float x) {
    if (fabsf(x) < 1e-5f) return __fmaf_rn(__fmul_rn(0.5f, x), x, x);
    return __fadd_rn(xla_exp(x), -1.0f);
}

__device__ __forceinline__ float xla_elu(float x) {
    return (x > 0.0f) ? x : xla_expm1(x);
}

// ---------------- threefry2x32 (JAX bit-exact) ------------------------------
__device__ __forceinline__ uint32_t rotl32(uint32_t v, int r) {
    return (v << r) | (v >> (32 - r));
}

__device__ __forceinline__ void threefry2x32(uint32_t k0, uint32_t k1,
                                             uint32_t x0, uint32_t x1,
                                             uint32_t& o0, uint32_t& o1) {
    uint32_t ks2 = k0 ^ k1 ^ 0x1BD11BDAu;
    x0 += k0; x1 += k1;
    x0 += x1; x1 = rotl32(x1, 13); x1 ^= x0;
    x0 += x1; x1 = rotl32(x1, 15); x1 ^= x0;
    x0 += x1; x1 = rotl32(x1, 26); x1 ^= x0;
    x0 += x1; x1 = rotl32(x1,  6); x1 ^= x0;
    x0 += k1; x1 += ks2 + 1u;
    x0 += x1; x1 = rotl32(x1, 17); x1 ^= x0;
    x0 += x1; x1 = rotl32(x1, 29); x1 ^= x0;
    x0 += x1; x1 = rotl32(x1, 16); x1 ^= x0;
    x0 += x1; x1 = rotl32(x1, 24); x1 ^= x0;
    x0 += ks2; x1 += k0 + 2u;
    x0 += x1; x1 = rotl32(x1, 13); x1 ^= x0;
    x0 += x1; x1 = rotl32(x1, 15); x1 ^= x0;
    x0 += x1; x1 = rotl32(x1, 26); x1 ^= x0;
    x0 += x1; x1 = rotl32(x1,  6); x1 ^= x0;
    x0 += k0; x1 += k1 + 3u;
    x0 += x1; x1 = rotl32(x1, 17); x1 ^= x0;
    x0 += x1; x1 = rotl32(x1, 29); x1 ^= x0;
    x0 += x1; x1 = rotl32(x1, 16); x1 ^= x0;
    x0 += x1; x1 = rotl32(x1, 24); x1 ^= x0;
    x0 += k1; x1 += ks2 + 4u;
    x0 += x1; x1 = rotl32(x1, 13); x1 ^= x0;
    x0 += x1; x1 = rotl32(x1, 15); x1 ^= x0;
    x0 += x1; x1 = rotl32(x1, 26); x1 ^= x0;
    x0 += x1; x1 = rotl32(x1,  6); x1 ^= x0;
    x0 += ks2; x1 += k0 + 5u;
    o0 = x0; o1 = x1;
}

__device__ __forceinline__ uint32_t jax_bits32(uint32_t k0, uint32_t k1, uint32_t i) {
    uint32_t o0, o1;
    threefry2x32(k0, k1, 0u, i, o0, o1);
    return o0 ^ o1;
}

// ---------------- counter sync helpers --------------------------------------
__device__ __forceinline__ void role_signal(int t, int slot) {
    __threadfence();                 // all threads: order my stores
    __syncthreads();                 // everyone's fence done
    if (threadIdx.x == 0) atomicAdd(&g_cnt[t][slot], 1);
}

__device__ __forceinline__ void role_wait(int t, int slot, int target) {
    if (threadIdx.x == 0) {
        while (atomicAdd(&g_cnt[t][slot], 0) < target) __nanosleep(64);
        __threadfence();
    }
    __syncthreads();
}

// ---------------- guarded float4 load ---------------------------------------
__device__ __forceinline__ float4 load_f4_guard(const float* __restrict__ src,
                                                size_t base, int k, int Klim) {
    if (k + 3 < Klim) return *reinterpret_cast<const float4*>(&src[base]);
    float4 v;
    v.x = (k + 0 < Klim) ? src[base + 0] : 0.f;
    v.y = (k + 1 < Klim) ? src[base + 1] : 0.f;
    v.z = (k + 2 < Klim) ? src[base + 2] : 0.f;
    v.w = (k + 3 < Klim) ? src[base + 3] : 0.f;
    return v;
}

// ---------------- GEMM core: 64x128, 4x8/thread, double-buffered ------------
// Per-output arithmetic: locked ascending-k single-accumulator FMA chain over
// BK=16 tiles — byte-identical to R11.
struct GemmSmem {
    float As[2][16][68];
    float Ws[2][16][128];
};

__device__ void gemm_core(GemmSmem* sm,
    const float* __restrict__ A, const float* __restrict__ W,
    const float* __restrict__ bias, float* __restrict__ C,
    int K, int N, bool act, bool fuse,
    const float* __restrict__ feat, int concatK, int bm, int bn)
{
    const int lda = fuse ? concatK : K;
    const int tid = threadIdx.x;
    const int tx = tid & 15;
    const int ty = tid >> 4;
    const int arow = tid >> 2, ac4 = tid & 3;
    const int wrow = tid >> 5, wcol4 = tid & 31;

    float acc[4][8];
#pragma unroll
    for (int i = 0; i < 4; i++)
#pragma unroll
        for (int j = 0; j < 8; j++) acc[i][j] = 0.f;

    const int ntiles = (K + 15) >> 4;

    float4 aR, wR0, wR1;
    auto load_tile = [&](int k0) {
        int ka = k0 + ac4 * 4;
        if (fuse && ka >= concatK)
            aR = load_f4_guard(feat, (size_t)(bm + arow) * FDIM + (ka - concatK), ka, K);
        else
            aR = load_f4_guard(A, (size_t)(bm + arow) * lda + ka, ka, K);

        int kw0 = k0 + wrow, kw1 = k0 + wrow + 8;
        int col = bn + wcol4 * 4;
        if (kw0 < K) {
            if (col + 3 < N) wR0 = *reinterpret_cast<const float4*>(&W[(size_t)kw0 * N + col]);
            else wR0 = load_f4_guard(W, (size_t)kw0 * N + col, col, N);
        } else wR0 = make_float4(0.f, 0.f, 0.f, 0.f);
        if (kw1 < K) {
            if (col + 3 < N) wR1 = *reinterpret_cast<const float4*>(&W[(size_t)kw1 * N + col]);
            else wR1 = load_f4_guard(W, (size_t)kw1 * N + col, col, N);
        } else wR1 = make_float4(0.f, 0.f, 0.f, 0.f);
    };
    auto store_tile = [&](int buf) {
        sm->As[buf][ac4 * 4 + 0][arow] = aR.x;
        sm->As[buf][ac4 * 4 + 1][arow] = aR.y;
        sm->As[buf][ac4 * 4 + 2][arow] = aR.z;
        sm->As[buf][ac4 * 4 + 3][arow] = aR.w;
        *reinterpret_cast<float4*>(&sm->Ws[buf][wrow][wcol4 * 4]) = wR0;
        *reinterpret_cast<float4*>(&sm->Ws[buf][wrow + 8][wcol4 * 4]) = wR1;
    };

    load_tile(0);
    store_tile(0);
    __syncthreads();

    int buf = 0;
    for (int tI = 0; tI < ntiles; tI++) {
        const bool more = (tI + 1 < ntiles);
        if (more) load_tile((tI + 1) << 4);

#pragma unroll
        for (int kk = 0; kk < 16; kk++) {
            float4 av  = *reinterpret_cast<const float4*>(&sm->As[buf][kk][ty * 4]);
            float4 wv0 = *reinterpret_cast<const float4*>(&sm->Ws[buf][kk][tx * 4]);
            float4 wv1 = *reinterpret_cast<const float4*>(&sm->Ws[buf][kk][64 + tx * 4]);
            float a_[4] = {av.x, av.y, av.z, av.w};
            float w_[8] = {wv0.x, wv0.y, wv0.z, wv0.w,
                           wv1.x, wv1.y, wv1.z, wv1.w};
#pragma unroll
            for (int i = 0; i < 4; i++)
#pragma unroll
                for (int j = 0; j < 8; j++)
                    acc[i][j] = __fmaf_rn(a_[i], w_[j], acc[i][j]);
        }
        if (more) {
            store_tile(buf ^ 1);
            __syncthreads();
            buf ^= 1;
        }
    }

    const bool fullN = (bn + 128 <= N);
#pragma unroll
    for (int i = 0; i < 4; i++) {
        int row = bm + ty * 4 + i;
#pragma unroll
        for (int h = 0; h < 2; h++) {
            int colb = bn + h * 64 + tx * 4;
            float v[4];
#pragma unroll
            for (int j = 0; j < 4; j++) {
                float x = acc[i][h * 4 + j];
                int col = colb + j;
                if (col < N) {
                    if (bias) x = __fadd_rn(x, bias[col]);
                    if (act) x = xla_elu(x);
                }
                v[j] = x;
            }
            if (fullN) {
                *reinterpret_cast<float4*>(&C[(size_t)row * N + colb]) =
                    make_float4(v[0], v[1], v[2], v[3]);
            } else {
#pragma unroll
                for (int j = 0; j < 4; j++)
                    if (colb + j < N) C[(size_t)row * N + colb + j] = v[j];
            }
        }
    }
}

// ---------------- per-step pipelined mega-kernel -----------------------------
// grid (4, 48, 7); z = role (dependency-ordered).
__global__ __launch_bounds__(256) void step_kernel(
    const float* __restrict__ W_ih, const float* __restrict__ W_hh,
    const float* __restrict__ Wp1,  const float* __restrict__ Wq1,
    const float* __restrict__ Wp2,  const float* __restrict__ Wq2,
    const float* __restrict__ b_ih, const float* __restrict__ b_hh,
    const float* __restrict__ bp1,  const float* __restrict__ bq1,
    const float* __restrict__ bp2,  const float* __restrict__ bq2,
    const float* __restrict__ W_in, const float* __restrict__ b_in,
    const int* __restrict__ actions,
    const float* __restrict__ feat,
    float* __restrict__ out_prior, float* __restrict__ out_post,
    int t, int last)
{
    __shared__ GemmSmem sm;
    const int z = blockIdx.z;
    const int bm = blockIdx.x * 64;
    const int bny = blockIdx.y;

    if (z == 0) {          // q1 = elu([h|feat] @ Wq1 + bq1)   K=3072, N=1000
        int bn = bny * 128;
        if (bn >= MLP) return;
        gemm_core(&sm, g_h, Wq1, bq1, g_q1, GRU_H + FDIM, MLP,
                  true, true, feat, GRU_H, bm, bn);
        role_signal(t, 0);
    } else if (z == 1) {   // gh_{t+1} = h @ W_hh + b_hh       K=2048, N=6144
        if (last) return;
        gemm_core(&sm, g_h, W_hh, b_hh, g_gh, GRU_H, G3,
                  false, false, nullptr, 0, bm, bny * 128);
    } else if (z == 2) {   // p1 = elu(h @ Wp1 + bp1)          K=2048, N=1000
        int bn = bny * 128;
        if (bn >= MLP) return;
        gemm_core(&sm, g_h, Wp1, bp1, g_p1, GRU_H, MLP,
                  true, false, nullptr, 0, bm, bn);
        role_signal(t, 1);
    } else if (z == 3) {   // post = q1 @ Wq2 + bq2            K=1000, N=1024
        int bn = bny * 128;
        if (bn >= ZF) return;
        role_wait(t, 0, 32);
        gemm_core(&sm, g_q1, Wq2, bq2, out_post, MLP, ZF,
                  false, false, nullptr, 0, bm, bn);
        role_signal(t, 2);
    } else if (z == 4) {   // prior = p1 @ Wp2 + bp2           K=1000, N=1024
        int bn = bny * 128;
        if (bn >= ZF) return;
        role_wait(t, 1, 32);
        gemm_core(&sm, g_p1, Wp2, bp2, out_prior, MLP, ZF,
                  false, false, nullptr, 0, bm, bn);
    } else if (z == 5) {   // sample z_t + x_{t+1}  (2 batches per block)
        if (last) return;
        int bid = blockIdx.x + 4 * blockIdx.y;
        if (bid >= 128) return;
        role_wait(t, 2, 32);

        __shared__ int   idx[2][32];
        __shared__ float wgt[2][32];

        int warp = threadIdx.x >> 5;
        int lane = threadIdx.x & 31;
        int half = warp >> 2;                  // 0 or 1
        int b = bid * 2 + half;
        int cw = warp & 3;

        uint32_t k0, k1;
        threefry2x32(0u, 42u, 0u, (uint32_t)t, k0, k1);
        const float TINY = 1.1754943508222875e-38f;

        for (int c = cw; c < 32; c += 4) {
            float l = out_post[(size_t)b * ZF + c * 32 + lane];
            uint32_t i = (uint32_t)((b * 32 + c) * 32 + lane);
            uint32_t bits = jax_bits32(k0, k1, i);
            float f = __fadd_rn(__uint_as_float((bits >> 9) | 0x3f800000u), -1.0f);
            float u = fmaxf(TINY, __fadd_rn(f, TINY));
            float g = -xla_log(-xla_log(u));
            float v = __fadd_rn(l, g);

            float bv = v; int bi = lane;
#pragma unroll
            for (int off = 16; off > 0; off >>= 1) {
                float ov = __shfl_down_sync(0xffffffffu, bv, off);
                int   oi = __shfl_down_sync(0xffffffffu, bi, off);
                if (ov > bv || (ov == bv && oi < bi)) { bv = ov; bi = oi; }
            }
            bi = __shfl_sync(0xffffffffu, bi, 0);

            float m = l;
#pragma unroll
            for (int off = 16; off > 0; off >>= 1)
                m = fmaxf(m, __shfl_xor_sync(0xffffffffu, m, off));
            float e = xla_exp(__fadd_rn(l, -m));
            float s = 0.f;
#pragma unroll
            for (int ll = 0; ll < 32; ll++)
                s = __fadd_rn(s, __shfl_sync(0xffffffffu, e, ll));
            float p = __fdiv_rn(e, s);
            float psel = __shfl_sync(0xffffffffu, p, bi);
            if (lane == 0) {
                idx[half][c] = bi;
                wgt[half][c] = __fadd_rn(__fadd_rn(1.0f, psel), -psel);  // fl(1+p)-p
            }
        }
        __syncthreads();

        // x_{t+1}: ascending-k chain (cats 0..31, action row, bias)
        int xh = threadIdx.x >> 7;              // 0 or 1
        int bx = bid * 2 + xh;
        int a = actions[t * B + bx];            // act_seq[t+1] = actions[t]
        for (int j = threadIdx.x & 127; j < MLP; j += 128) {
            float s = 0.f;
#pragma unroll
            for (int c = 0; c < 32; c++)
                s = __fmaf_rn(wgt[xh][c], W_in[(size_t)(c * 32 + idx[xh][c]) * MLP + j], s);
            s = __fmaf_rn(1.0f, W_in[(size_t)(ZF + a) * MLP + j], s);
            s = __fadd_rn(s, b_in[j]);
            g_x[bx * MLP + j] = xla_elu(s);
        }
        role_signal(t, 3);
    } else {               // z==6: gi_{t+1} = x @ W_ih + b_ih  K=1000, N=6144
        if (last) return;
        role_wait(t, 3, 128);
        gemm_core(&sm, g_x, W_ih, b_ih, g_gi, MLP, G3,
                  false, false, nullptr, 0, bm, bny * 128);
    }
}

// ---------------- GRU gate pointwise (float4) -------------------------------
__global__ __launch_bounds__(256) void gru_kernel()
{
    int i4 = blockIdx.x * blockDim.x + threadIdx.x;
    int b = i4 >> 9;
    int j4 = i4 & 511;
    const float4* gib = reinterpret_cast<const float4*>(g_gi + (size_t)b * G3);
    const float4* ghb = reinterpret_cast<const float4*>(g_gh + (size_t)b * G3);
    float4 ir4 = gib[j4],        hr4 = ghb[j4];
    float4 iz4 = gib[512 + j4],  hz4 = ghb[512 + j4];
    float4 in4 = gib[1024 + j4], hn4 = ghb[1024 + j4];
    float4 hp4 = reinterpret_cast<const float4*>(g_h)[i4];
    float4 o;
    {
        float r  = xla_sigmoid(__fadd_rn(ir4.x, hr4.x));
        float zg = xla_sigmoid(__fadd_rn(iz4.x, hz4.x));
        float n  = xla_tanh(__fmaf_rn(r, hn4.x, in4.x));
        o.x = __fmaf_rn(zg, hp4.x, __fmul_rn(__fsub_rn(1.0f, zg), n));
    }
    {
        float r  = xla_sigmoid(__fadd_rn(ir4.y, hr4.y));
        float zg = xla_sigmoid(__fadd_rn(iz4.y, hz4.y));
        float n  = xla_tanh(__fmaf_rn(r, hn4.y, in4.y));
        o.y = __fmaf_rn(zg, hp4.y, __fmul_rn(__fsub_rn(1.0f, zg), n));
    }
    {
        float r  = xla_sigmoid(__fadd_rn(ir4.z, hr4.z));
        float zg = xla_sigmoid(__fadd_rn(iz4.z, hz4.z));
        float n  = xla_tanh(__fmaf_rn(r, hn4.z, in4.z));
        o.z = __fmaf_rn(zg, hp4.z, __fmul_rn(__fsub_rn(1.0f, zg), n));
    }
    {
        float r  = xla_sigmoid(__fadd_rn(ir4.w, hr4.w));
        float zg = xla_sigmoid(__fadd_rn(iz4.w, hz4.w));
        float n  = xla_tanh(__fmaf_rn(r, hn4.w, in4.w));
        o.w = __fmaf_rn(zg, hp4.w, __fmul_rn(__fsub_rn(1.0f, zg), n));
    }
    reinterpret_cast<float4*>(g_h)[i4] = o;
}

// ---------------- prologue kernels -------------------------------------------
__global__ __launch_bounds__(256) void reset_kernel()
{
    int i = blockIdx.x * blockDim.x + threadIdx.x;
    if (i < T_STEPS * 4) (&g_cnt[0][0])[i] = 0;
    for (int j = i; j < B * GRU_H; j += gridDim.x * blockDim.x) g_h[j] = 0.f;
}

__global__ __launch_bounds__(256) void compute_x0_kernel(
    const float* __restrict__ W_in, const float* __restrict__ b_in)
{
    int b = blockIdx.x;
    for (int j = threadIdx.x; j < MLP; j += blockDim.x) {
        float s = W_in[(size_t)ZF * MLP + j];   // action 0 row, weight 1
        s = __fadd_rn(s, b_in[j]);
        g_x[b * MLP + j] = xla_elu(s);
    }
}

// prologue dual GEMM: gi_0 | gh_0 (z selects), grid (4, 48, 2)
__global__ __launch_bounds__(256) void gemm0_kernel(
    const float* __restrict__ W_ih, const float* __restrict__ W_hh,
    const float* __restrict__ b_ih, const float* __restrict__ b_hh)
{
    __shared__ GemmSmem sm;
    const int bm = blockIdx.x * 64;
    const int bn = blockIdx.y * 128;
    if (blockIdx.z == 0)
        gemm_core(&sm, g_x, W_ih, b_ih, g_gi, MLP, G3, false, false, nullptr, 0, bm, bn);
    else
        gemm_core(&sm, g_h, W_hh, b_hh, g_gh, GRU_H, G3, false, false, nullptr, 0, bm, bn);
}

// ---------------------------------------------------------------------------
extern "C" void kernel_launch(void* const* d_in, const int* in_sizes, int n_in,
                              void* d_out, int out_size)
{
    const float* features = (const float*)d_in[0];   // [64,256,1024]
    const int*   actions  = (const int*)  d_in[1];   // [64,256]
    const float* W_in = (const float*)d_in[2];
    const float* b_in = (const float*)d_in[3];
    const float* W_ih = (const float*)d_in[4];
    const float* W_hh = (const float*)d_in[5];
    const float* b_ih = (const float*)d_in[6];
    const float* b_hh = (const float*)d_in[7];
    const float* Wp1  = (const float*)d_in[8];
    const float* bp1  = (const float*)d_in[9];
    const float* Wp2  = (const float*)d_in[10];
    const float* bp2  = (const float*)d_in[11];
    const float* Wq1  = (const float*)d_in[12];
    const float* bq1  = (const float*)d_in[13];
    const float* Wq2  = (const float*)d_in[14];
    const float* bq2  = (const float*)d_in[15];
    float* out = (float*)d_out;                      // [2,64,256,32,32]

    // prologue: reset counters + h=0; x_0; [gi_0 | gh_0]
    reset_kernel<<<(B * GRU_H + 255) / 256, 256>>>();
    compute_x0_kernel<<<B, 256>>>(W_in, b_in);
    gemm0_kernel<<<dim3(4, 48, 2), 256>>>(W_ih, W_hh, b_ih, b_hh);

    for (int t = 0; t < T_STEPS; t++) {
        const float* feat_t = features + (size_t)t * B * FDIM;
        float* out_prior = out + (size_t)t * B * ZF;
        float* out_post  = out + ((size_t)(T_STEPS + t)) * B * ZF;

        gru_kernel<<<(B * GRU_H / 4) / 256, 256>>>();

        step_kernel<<<dim3(4, 48, 7), 256>>>(
            W_ih, W_hh, Wp1, Wq1, Wp2, Wq2,
            b_ih, b_hh, bp1, bq1, bp2, bq2,
            W_in, b_in, actions, feat_t, out_prior, out_post,
            t, (t == T_STEPS - 1) ? 1 : 0);
    }
}

// round 13
// speedup vs baseline: 3.4833x; 1.2565x over previous
#include <cuda_runtime.h>
#include <cstdint>

// ---------------------------------------------------------------------------
// RSSMCore: T=64 sequential steps, B=256.  PASSING MODEL (locked since R6):
//  * RNG: jax_threefry_partitionable: bits(i) = o0^o1 of threefry(key,(0,i)).
//  * GEMM: exact f32, per-output ascending-k single-accumulator FMA chain
//    (BK=16 tiles ascending) — flip-free at rel_err 9.051719e-07.
//    Per-output arithmetic MUST NOT change (tile shape / scheduling may).
//  * z weights w = fl(1+p)-p carried into the W_in gather.
//  * XLA rational tanh / logistic / cephes exp/log, FMA-form.
// R12 kept: single-launch per-step pipeline, counter sync, monotone roles.
// Round 13 (perf only): WIDEN THE CRITICAL CHAIN.
//  q1 and post now use 32x64 tiles -> 128 blocks each (were 32) so the chain
//  gru->q1->post->sample->gi completes inside the gh bulk instead of
//  dangling past it. GEMM core templated on (BM,BN); identical per-output
//  arithmetic. Grid (192,7), roles dependency-ordered on blockIdx.y.
// ---------------------------------------------------------------------------

#define T_STEPS 64
#define B 256
#define GRU_H 2048
#define MLP 1000
#define ZF 1024
#define FDIM 1024
#define G3 (3 * GRU_H)   // 6144

// ---------------- scratch (device globals; no allocation allowed) ----------
__device__ float g_x[B * MLP];
__device__ float g_gi[B * G3];
__device__ float g_gh[B * G3];
__device__ float g_h[B * GRU_H];
__device__ float g_p1[B * MLP];
__device__ float g_q1[B * MLP];
__device__ int   g_cnt[T_STEPS][4];   // 0:q1 1:p1 2:post 3:x

// =================== XLA-matched elementwise math (FMA form) ================

__device__ __forceinline__ float xla_tanh(float x) {
    if (fabsf(x) < 0.0004f) return x;
    float xc = fminf(fmaxf(x, -7.90531110763549805f), 7.90531110763549805f);
    float x2 = __fmul_rn(xc, xc);
    float p = -2.76076847742355e-16f;
    p = __fmaf_rn(p, x2, 2.00018790482477e-13f);
    p = __fmaf_rn(p, x2, -8.60467152213735e-11f);
    p = __fmaf_rn(p, x2, 5.12229709037114e-08f);
    p = __fmaf_rn(p, x2, 1.48572235717979e-05f);
    p = __fmaf_rn(p, x2, 6.37261928875436e-04f);
    p = __fmaf_rn(p, x2, 4.89352455891786e-03f);
    p = __fmul_rn(p, xc);
    float q = 1.19825839466702e-06f;
    q = __fmaf_rn(q, x2, 1.18534705686654e-04f);
    q = __fmaf_rn(q, x2, 2.26843463243900e-03f);
    q = __fmaf_rn(q, x2, 4.89352518554385e-03f);
    return __fdiv_rn(p, q);
}

__device__ __forceinline__ float xla_sigmoid(float x) {
    return __fmaf_rn(0.5f, xla_tanh(__fmul_rn(0.5f, x)), 0.5f);
}

__device__ __forceinline__ float xla_log(float a) {
    int ix = __float_as_int(a);
    float e = (float)((ix >> 23) - 126);
    float m = __int_as_float((ix & 0x007fffff) | 0x3f000000);
    if (m < 0.707106781186547524f) { e = __fadd_rn(e, -1.0f); m = __fadd_rn(m, m); }
    m = __fadd_rn(m, -1.0f);
    float z = __fmul_rn(m, m);
    float y = 7.0376836292e-2f;
    y = __fmaf_rn(y, m, -1.1514610310e-1f);
    y = __fmaf_rn(y, m, 1.1676998740e-1f);
    y = __fmaf_rn(y, m, -1.2420140846e-1f);
    y = __fmaf_rn(y, m, 1.4249322787e-1f);
    y = __fmaf_rn(y, m, -1.6668057665e-1f);
    y = __fmaf_rn(y, m, 2.0000714765e-1f);
    y = __fmaf_rn(y, m, -2.4999993993e-1f);
    y = __fmaf_rn(y, m, 3.3333331174e-1f);
    y = __fmul_rn(__fmul_rn(y, m), z);
    y = __fmaf_rn(e, -2.12194440e-4f, y);
    y = __fmaf_rn(z, -0.5f, y);
    float r = __fadd_rn(m, y);
    r = __fmaf_rn(e, 0.693359375f, r);
    return r;
}

__device__ __forceinline__ float xla_exp(float x) {
    float xc = fminf(fmaxf(x, -87.33654f), 88.72283f);
    float m = floorf(__fmaf_rn(xc, 1.44269504088896341f, 0.5f));
    float r = __fmaf_rn(m, -0.693359375f, xc);
    r = __fmaf_rn(m, 2.12194440e-4f, r);
    float r2 = __fmul_rn(r, r);
    float p = 1.9875691500e-4f;
    p = __fmaf_rn(p, r, 1.3981999507e-3f);
    p = __fmaf_rn(p, r, 8.3334519073e-3f);
    p = __fmaf_rn(p, r, 4.1665795894e-2f);
    p = __fmaf_rn(p, r, 1.6666665459e-1f);
    p = __fmaf_rn(p, r, 5.0000001201e-1f);
    float y = __fadd_rn(__fmaf_rn(p, r2, r), 1.0f);
    return __fmul_rn(y, __int_as_float(((int)m + 127) << 23));
}

__device__ __forceinline__ float xla_expm1(float x) {
    if (fabsf(x) < 1e-5f) return __fmaf_rn(__fmul_rn(0.5f, x), x, x);
    return __fadd_rn(xla_exp(x), -1.0f);
}

__device__ __forceinline__ float xla_elu(float x) {
    return (x > 0.0f) ? x : xla_expm1(x);
}

// ---------------- threefry2x32 (JAX bit-exact) ------------------------------
__device__ __forceinline__ uint32_t rotl32(uint32_t v, int r) {
    return (v << r) | (v >> (32 - r));
}

__device__ __forceinline__ void threefry2x32(uint32_t k0, uint32_t k1,
                                             uint32_t x0, uint32_t x1,
                                             uint32_t& o0, uint32_t& o1) {
    uint32_t ks2 = k0 ^ k1 ^ 0x1BD11BDAu;
    x0 += k0; x1 += k1;
    x0 += x1; x1 = rotl32(x1, 13); x1 ^= x0;
    x0 += x1; x1 = rotl32(x1, 15); x1 ^= x0;
    x0 += x1; x1 = rotl32(x1, 26); x1 ^= x0;
    x0 += x1; x1 = rotl32(x1,  6); x1 ^= x0;
    x0 += k1; x1 += ks2 + 1u;
    x0 += x1; x1 = rotl32(x1, 17); x1 ^= x0;
    x0 += x1; x1 = rotl32(x1, 29); x1 ^= x0;
    x0 += x1; x1 = rotl32(x1, 16); x1 ^= x0;
    x0 += x1; x1 = rotl32(x1, 24); x1 ^= x0;
    x0 += ks2; x1 += k0 + 2u;
    x0 += x1; x1 = rotl32(x1, 13); x1 ^= x0;
    x0 += x1; x1 = rotl32(x1, 15); x1 ^= x0;
    x0 += x1; x1 = rotl32(x1, 26); x1 ^= x0;
    x0 += x1; x1 = rotl32(x1,  6); x1 ^= x0;
    x0 += k0; x1 += k1 + 3u;
    x0 += x1; x1 = rotl32(x1, 17); x1 ^= x0;
    x0 += x1; x1 = rotl32(x1, 29); x1 ^= x0;
    x0 += x1; x1 = rotl32(x1, 16); x1 ^= x0;
    x0 += x1; x1 = rotl32(x1, 24); x1 ^= x0;
    x0 += k1; x1 += ks2 + 4u;
    x0 += x1; x1 = rotl32(x1, 13); x1 ^= x0;
    x0 += x1; x1 = rotl32(x1, 15); x1 ^= x0;
    x0 += x1; x1 = rotl32(x1, 26); x1 ^= x0;
    x0 += x1; x1 = rotl32(x1,  6); x1 ^= x0;
    x0 += ks2; x1 += k0 + 5u;
    o0 = x0; o1 = x1;
}

__device__ __forceinline__ uint32_t jax_bits32(uint32_t k0, uint32_t k1, uint32_t i) {
    uint32_t o0, o1;
    threefry2x32(k0, k1, 0u, i, o0, o1);
    return o0 ^ o1;
}

// ---------------- counter sync helpers --------------------------------------
__device__ __forceinline__ void role_signal(int t, int slot) {
    __threadfence();
    __syncthreads();
    if (threadIdx.x == 0) atomicAdd(&g_cnt[t][slot], 1);
}

__device__ __forceinline__ void role_wait(int t, int slot, int target) {
    if (threadIdx.x == 0) {
        while (atomicAdd(&g_cnt[t][slot], 0) < target) __nanosleep(64);
        __threadfence();
    }
    __syncthreads();
}

// ---------------- guarded float4 load ---------------------------------------
__device__ __forceinline__ float4 load_f4_guard(const float* __restrict__ src,
                                                size_t base, int k, int Klim) {
    if (k + 3 < Klim) return *reinterpret_cast<const float4*>(&src[base]);
    float4 v;
    v.x = (k + 0 < Klim) ? src[base + 0] : 0.f;
    v.y = (k + 1 < Klim) ? src[base + 1] : 0.f;
    v.z = (k + 2 < Klim) ? src[base + 2] : 0.f;
    v.w = (k + 3 < Klim) ? src[base + 3] : 0.f;
    return v;
}

// ---------------- templated GEMM core: BMxBN, double-buffered ----------------
// Per-output arithmetic: locked ascending-k single-accumulator FMA chain over
// BK=16 tiles — identical to R11/R12 for every (row,col) output.
#define SMEM_BYTES 25088   // sizeof largest variant (64x128)

template<int BM, int BN>
__device__ void gemm_core_t(char* smraw,
    const float* __restrict__ A, const float* __restrict__ W,
    const float* __restrict__ bias, float* __restrict__ C,
    int K, int N, bool act, bool fuse,
    const float* __restrict__ feat, int concatK, int bm, int bn)
{
    struct Sm { float As[2][16][BM + 4]; float Ws[2][16][BN]; };
    Sm* sm = reinterpret_cast<Sm*>(smraw);
    constexpr int TM = BM / 16;
    constexpr int TN = BN / 16;
    constexpr int NW = BN / 64;          // float4 W loads per thread
    const int lda = fuse ? concatK : K;
    const int tid = threadIdx.x;
    const int tx = tid & 15;
    const int ty = tid >> 4;
    const int arow = tid >> 2, ac4 = tid & 3;          // A staging (tid < BM*4)
    const int wrow  = (NW == 2) ? (tid >> 5) : (tid >> 4);
    const int wcol4 = (NW == 2) ? (tid & 31) : (tid & 15);

    float acc[TM][TN];
#pragma unroll
    for (int i = 0; i < TM; i++)
#pragma unroll
        for (int j = 0; j < TN; j++) acc[i][j] = 0.f;

    const int ntiles = (K + 15) >> 4;

    float4 aR, wR0, wR1;
    auto load_tile = [&](int k0) {
        if (BM * 4 == 256 || tid < BM * 4) {
            int ka = k0 + ac4 * 4;
            if (fuse && ka >= concatK)
                aR = load_f4_guard(feat, (size_t)(bm + arow) * FDIM + (ka - concatK), ka, K);
            else
                aR = load_f4_guard(A, (size_t)(bm + arow) * lda + ka, ka, K);
        }
        int col = bn + wcol4 * 4;
        int kw0 = k0 + wrow;
        if (kw0 < K) {
            if (col + 3 < N) wR0 = *reinterpret_cast<const float4*>(&W[(size_t)kw0 * N + col]);
            else wR0 = load_f4_guard(W, (size_t)kw0 * N + col, col, N);
        } else wR0 = make_float4(0.f, 0.f, 0.f, 0.f);
        if (NW == 2) {
            int kw1 = k0 + wrow + 8;
            if (kw1 < K) {
                if (col + 3 < N) wR1 = *reinterpret_cast<const float4*>(&W[(size_t)kw1 * N + col]);
                else wR1 = load_f4_guard(W, (size_t)kw1 * N + col, col, N);
            } else wR1 = make_float4(0.f, 0.f, 0.f, 0.f);
        }
    };
    auto store_tile = [&](int buf) {
        if (BM * 4 == 256 || tid < BM * 4) {
            sm->As[buf][ac4 * 4 + 0][arow] = aR.x;
            sm->As[buf][ac4 * 4 + 1][arow] = aR.y;
            sm->As[buf][ac4 * 4 + 2][arow] = aR.z;
            sm->As[buf][ac4 * 4 + 3][arow] = aR.w;
        }
        *reinterpret_cast<float4*>(&sm->Ws[buf][wrow][wcol4 * 4]) = wR0;
        if (NW == 2)
            *reinterpret_cast<float4*>(&sm->Ws[buf][wrow + 8][wcol4 * 4]) = wR1;
    };

    load_tile(0);
    store_tile(0);
    __syncthreads();

    int buf = 0;
    for (int tI = 0; tI < ntiles; tI++) {
        const bool more = (tI + 1 < ntiles);
        if (more) load_tile((tI + 1) << 4);

#pragma unroll
        for (int kk = 0; kk < 16; kk++) {
            float a_[TM];
            if (TM == 4) {
                float4 av = *reinterpret_cast<const float4*>(&sm->As[buf][kk][ty * 4]);
                a_[0] = av.x; a_[1] = av.y; a_[2] = av.z; a_[TM - 1] = av.w;
            } else {
                float2 av = *reinterpret_cast<const float2*>(&sm->As[buf][kk][ty * 2]);
                a_[0] = av.x; a_[TM - 1] = av.y;
            }
            float w_[TN];
            {
                float4 wv0 = *reinterpret_cast<const float4*>(&sm->Ws[buf][kk][tx * 4]);
                w_[0] = wv0.x; w_[1] = wv0.y; w_[2] = wv0.z; w_[3] = wv0.w;
            }
            if (TN == 8) {
                float4 wv1 = *reinterpret_cast<const float4*>(&sm->Ws[buf][kk][64 + tx * 4]);
                w_[TN - 4] = wv1.x; w_[TN - 3] = wv1.y; w_[TN - 2] = wv1.z; w_[TN - 1] = wv1.w;
            }
#pragma unroll
            for (int i = 0; i < TM; i++)
#pragma unroll
                for (int j = 0; j < TN; j++)
                    acc[i][j] = __fmaf_rn(a_[i], w_[j], acc[i][j]);
        }
        if (more) {
            store_tile(buf ^ 1);
            __syncthreads();
            buf ^= 1;
        }
    }

    const bool fullN = (bn + BN <= N);
#pragma unroll
    for (int i = 0; i < TM; i++) {
        int row = bm + ty * TM + i;
#pragma unroll
        for (int h = 0; h < TN / 4; h++) {
            int colb = bn + h * 64 + tx * 4;
            float v[4];
#pragma unroll
            for (int j = 0; j < 4; j++) {
                float x = acc[i][h * 4 + j];
                int col = colb + j;
                if (col < N) {
                    if (bias) x = __fadd_rn(x, bias[col]);
                    if (act) x = xla_elu(x);
                }
                v[j] = x;
            }
            if (fullN) {
                *reinterpret_cast<float4*>(&C[(size_t)row * N + colb]) =
                    make_float4(v[0], v[1], v[2], v[3]);
            } else {
#pragma unroll
                for (int j = 0; j < 4; j++)
                    if (colb + j < N) C[(size_t)row * N + colb + j] = v[j];
            }
        }
    }
}

// ---------------- per-step pipelined mega-kernel -----------------------------
// grid (192, 7); blockIdx.y = role in dependency order:
//  y0 q1(32x64,128blk) | y1 gh(64x128,192) | y2 p1(64x128,32) |
//  y3 post(32x64,128, wait q1) | y4 prior(64x128,32, wait p1) |
//  y5 sample+x(128, wait post) | y6 gi(64x128,192, wait x)
__global__ __launch_bounds__(256) void step_kernel(
    const float* __restrict__ W_ih, const float* __restrict__ W_hh,
    const float* __restrict__ Wp1,  const float* __restrict__ Wq1,
    const float* __restrict__ Wp2,  const float* __restrict__ Wq2,
    const float* __restrict__ b_ih, const float* __restrict__ b_hh,
    const float* __restrict__ bp1,  const float* __restrict__ bq1,
    const float* __restrict__ bp2,  const float* __restrict__ bq2,
    const float* __restrict__ W_in, const float* __restrict__ b_in,
    const int* __restrict__ actions,
    const float* __restrict__ feat,
    float* __restrict__ out_prior, float* __restrict__ out_post,
    int t, int last)
{
    __shared__ __align__(16) char smraw[SMEM_BYTES];
    const int role = blockIdx.y;
    const int bid = blockIdx.x;            // 0..191

    if (role == 0) {        // q1 = elu([h|feat] @ Wq1 + bq1)  K=3072, N=1000
        if (bid >= 128) return;
        int bm = (bid & 7) * 32, bn = (bid >> 3) * 64;
        gemm_core_t<32, 64>(smraw, g_h, Wq1, bq1, g_q1, GRU_H + FDIM, MLP,
                            true, true, feat, GRU_H, bm, bn);
        role_signal(t, 0);
    } else if (role == 1) { // gh_{t+1} = h @ W_hh + b_hh      K=2048, N=6144
        if (last) return;
        gemm_core_t<64, 128>(smraw, g_h, W_hh, b_hh, g_gh, GRU_H, G3,
                             false, false, nullptr, 0, (bid & 3) * 64, (bid >> 2) * 128);
    } else if (role == 2) { // p1 = elu(h @ Wp1 + bp1)         K=2048, N=1000
        if (bid >= 32) return;
        gemm_core_t<64, 128>(smraw, g_h, Wp1, bp1, g_p1, GRU_H, MLP,
                             true, false, nullptr, 0, (bid & 3) * 64, (bid >> 2) * 128);
        role_signal(t, 1);
    } else if (role == 3) { // post = q1 @ Wq2 + bq2           K=1000, N=1024
        if (bid >= 128) return;
        role_wait(t, 0, 128);
        int bm = (bid & 7) * 32, bn = (bid >> 3) * 64;
        gemm_core_t<32, 64>(smraw, g_q1, Wq2, bq2, out_post, MLP, ZF,
                            false, false, nullptr, 0, bm, bn);
        role_signal(t, 2);
    } else if (role == 4) { // prior = p1 @ Wp2 + bp2          K=1000, N=1024
        if (bid >= 32) return;
        role_wait(t, 1, 32);
        gemm_core_t<64, 128>(smraw, g_p1, Wp2, bp2, out_prior, MLP, ZF,
                             false, false, nullptr, 0, (bid & 3) * 64, (bid >> 2) * 128);
    } else if (role == 5) { // sample z_t + x_{t+1}  (2 batches per block)
        if (last) return;
        if (bid >= 128) return;
        role_wait(t, 2, 128);

        __shared__ int   idx[2][32];
        __shared__ float wgt[2][32];

        int warp = threadIdx.x >> 5;
        int lane = threadIdx.x & 31;
        int half = warp >> 2;
        int b = bid * 2 + half;
        int cw = warp & 3;

        uint32_t k0, k1;
        threefry2x32(0u, 42u, 0u, (uint32_t)t, k0, k1);
        const float TINY = 1.1754943508222875e-38f;

        for (int c = cw; c < 32; c += 4) {
            float l = out_post[(size_t)b * ZF + c * 32 + lane];
            uint32_t i = (uint32_t)((b * 32 + c) * 32 + lane);
            uint32_t bits = jax_bits32(k0, k1, i);
            float f = __fadd_rn(__uint_as_float((bits >> 9) | 0x3f800000u), -1.0f);
            float u = fmaxf(TINY, __fadd_rn(f, TINY));
            float g = -xla_log(-xla_log(u));
            float v = __fadd_rn(l, g);

            float bv = v; int bi = lane;
#pragma unroll
            for (int off = 16; off > 0; off >>= 1) {
                float ov = __shfl_down_sync(0xffffffffu, bv, off);
                int   oi = __shfl_down_sync(0xffffffffu, bi, off);
                if (ov > bv || (ov == bv && oi < bi)) { bv = ov; bi = oi; }
            }
            bi = __shfl_sync(0xffffffffu, bi, 0);

            float m = l;
#pragma unroll
            for (int off = 16; off > 0; off >>= 1)
                m = fmaxf(m, __shfl_xor_sync(0xffffffffu, m, off));
            float e = xla_exp(__fadd_rn(l, -m));
            float s = 0.f;
#pragma unroll
            for (int ll = 0; ll < 32; ll++)
                s = __fadd_rn(s, __shfl_sync(0xffffffffu, e, ll));
            float p = __fdiv_rn(e, s);
            float psel = __shfl_sync(0xffffffffu, p, bi);
            if (lane == 0) {
                idx[half][c] = bi;
                wgt[half][c] = __fadd_rn(__fadd_rn(1.0f, psel), -psel);  // fl(1+p)-p
            }
        }
        __syncthreads();

        int xh = threadIdx.x >> 7;
        int bx = bid * 2 + xh;
        int a = actions[t * B + bx];        // act_seq[t+1] = actions[t]
        for (int j = threadIdx.x & 127; j < MLP; j += 128) {
            float s = 0.f;
#pragma unroll
            for (int c = 0; c < 32; c++)
                s = __fmaf_rn(wgt[xh][c], W_in[(size_t)(c * 32 + idx[xh][c]) * MLP + j], s);
            s = __fmaf_rn(1.0f, W_in[(size_t)(ZF + a) * MLP + j], s);
            s = __fadd_rn(s, b_in[j]);
            g_x[bx * MLP + j] = xla_elu(s);
        }
        role_signal(t, 3);
    } else {                // role 6: gi_{t+1} = x @ W_ih + b_ih  K=1000, N=6144
        if (last) return;
        role_wait(t, 3, 128);
        gemm_core_t<64, 128>(smraw, g_x, W_ih, b_ih, g_gi, MLP, G3,
                             false, false, nullptr, 0, (bid & 3) * 64, (bid >> 2) * 128);
    }
}

// ---------------- GRU gate pointwise (float4) -------------------------------
__global__ __launch_bounds__(256) void gru_kernel()
{
    int i4 = blockIdx.x * blockDim.x + threadIdx.x;
    int b = i4 >> 9;
    int j4 = i4 & 511;
    const float4* gib = reinterpret_cast<const float4*>(g_gi + (size_t)b * G3);
    const float4* ghb = reinterpret_cast<const float4*>(g_gh + (size_t)b * G3);
    float4 ir4 = gib[j4],        hr4 = ghb[j4];
    float4 iz4 = gib[512 + j4],  hz4 = ghb[512 + j4];
    float4 in4 = gib[1024 + j4], hn4 = ghb[1024 + j4];
    float4 hp4 = reinterpret_cast<const float4*>(g_h)[i4];
    float4 o;
    {
        float r  = xla_sigmoid(__fadd_rn(ir4.x, hr4.x));
        float zg = xla_sigmoid(__fadd_rn(iz4.x, hz4.x));
        float n  = xla_tanh(__fmaf_rn(r, hn4.x, in4.x));
        o.x = __fmaf_rn(zg, hp4.x, __fmul_rn(__fsub_rn(1.0f, zg), n));
    }
    {
        float r  = xla_sigmoid(__fadd_rn(ir4.y, hr4.y));
        float zg = xla_sigmoid(__fadd_rn(iz4.y, hz4.y));
        float n  = xla_tanh(__fmaf_rn(r, hn4.y, in4.y));
        o.y = __fmaf_rn(zg, hp4.y, __fmul_rn(__fsub_rn(1.0f, zg), n));
    }
    {
        float r  = xla_sigmoid(__fadd_rn(ir4.z, hr4.z));
        float zg = xla_sigmoid(__fadd_rn(iz4.z, hz4.z));
        float n  = xla_tanh(__fmaf_rn(r, hn4.z, in4.z));
        o.z = __fmaf_rn(zg, hp4.z, __fmul_rn(__fsub_rn(1.0f, zg), n));
    }
    {
        float r  = xla_sigmoid(__fadd_rn(ir4.w, hr4.w));
        float zg = xla_sigmoid(__fadd_rn(iz4.w, hz4.w));
        float n  = xla_tanh(__fmaf_rn(r, hn4.w, in4.w));
        o.w = __fmaf_rn(zg, hp4.w, __fmul_rn(__fsub_rn(1.0f, zg), n));
    }
    reinterpret_cast<float4*>(g_h)[i4] = o;
}

// ---------------- prologue kernels -------------------------------------------
__global__ __launch_bounds__(256) void reset_kernel()
{
    int i = blockIdx.x * blockDim.x + threadIdx.x;
    if (i < T_STEPS * 4) (&g_cnt[0][0])[i] = 0;
    for (int j = i; j < B * GRU_H; j += gridDim.x * blockDim.x) g_h[j] = 0.f;
}

__global__ __launch_bounds__(256) void compute_x0_kernel(
    const float* __restrict__ W_in, const float* __restrict__ b_in)
{
    int b = blockIdx.x;
    for (int j = threadIdx.x; j < MLP; j += blockDim.x) {
        float s = W_in[(size_t)ZF * MLP + j];   // action 0 row, weight 1
        s = __fadd_rn(s, b_in[j]);
        g_x[b * MLP + j] = xla_elu(s);
    }
}

// prologue dual GEMM: gi_0 | gh_0 (z selects), grid (4, 48, 2)
__global__ __launch_bounds__(256) void gemm0_kernel(
    const float* __restrict__ W_ih, const float* __restrict__ W_hh,
    const float* __restrict__ b_ih, const float* __restrict__ b_hh)
{
    __shared__ __align__(16) char smraw[SMEM_BYTES];
    const int bm = blockIdx.x * 64;
    const int bn = blockIdx.y * 128;
    if (blockIdx.z == 0)
        gemm_core_t<64, 128>(smraw, g_x, W_ih, b_ih, g_gi, MLP, G3,
                             false, false, nullptr, 0, bm, bn);
    else
        gemm_core_t<64, 128>(smraw, g_h, W_hh, b_hh, g_gh, GRU_H, G3,
                             false, false, nullptr, 0, bm, bn);
}

// ---------------------------------------------------------------------------
extern "C" void kernel_launch(void* const* d_in, const int* in_sizes, int n_in,
                              void* d_out, int out_size)
{
    const float* features = (const float*)d_in[0];   // [64,256,1024]
    const int*   actions  = (const int*)  d_in[1];   // [64,256]
    const float* W_in = (const float*)d_in[2];
    const float* b_in = (const float*)d_in[3];
    const float* W_ih = (const float*)d_in[4];
    const float* W_hh = (const float*)d_in[5];
    const float* b_ih = (const float*)d_in[6];
    const float* b_hh = (const float*)d_in[7];
    const float* Wp1  = (const float*)d_in[8];
    const float* bp1  = (const float*)d_in[9];
    const float* Wp2  = (const float*)d_in[10];
    const float* bp2  = (const float*)d_in[11];
    const float* Wq1  = (const float*)d_in[12];
    const float* bq1  = (const float*)d_in[13];
    const float* Wq2  = (const float*)d_in[14];
    const float* bq2  = (const float*)d_in[15];
    float* out = (float*)d_out;                      // [2,64,256,32,32]

    reset_kernel<<<(B * GRU_H + 255) / 256, 256>>>();
    compute_x0_kernel<<<B, 256>>>(W_in, b_in);
    gemm0_kernel<<<dim3(4, 48, 2), 256>>>(W_ih, W_hh, b_ih, b_hh);

    for (int t = 0; t < T_STEPS; t++) {
        const float* feat_t = features + (size_t)t * B * FDIM;
        float* out_prior = out + (size_t)t * B * ZF;
        float* out_post  = out + ((size_t)(T_STEPS + t)) * B * ZF;

        gru_kernel<<<(B * GRU_H / 4) / 256, 256>>>();

        step_kernel<<<dim3(192, 7), 256>>>(
            W_ih, W_hh, Wp1, Wq1, Wp2, Wq2,
            b_ih, b_hh, bp1, bq1, bp2, bq2,
            W_in, b_in, actions, feat_t, out_prior, out_post,
            t, (t == T_STEPS - 1) ? 1 : 0);
    }
}